// round 1
// baseline (speedup 1.0000x reference)
#include <cuda_runtime.h>
#include <math.h>

#define BB 8
#define SS 1024
#define NH 16
#define DKV 64
#define DMODEL 1024
#define MTOT (BB*SS)

// scratch: q,k,v in [B,H,S,64] layout, fp32 (q pre-scaled by 1/8)
__device__ float g_q[BB*NH*SS*DKV];
__device__ float g_k[BB*NH*SS*DKV];
__device__ float g_v[BB*NH*SS*DKV];

// ---------------------------------------------------------------------------
// Projection GEMM: Out = X[8192,1024] @ W[1024,1024] + bias, scattered to
// [B,H,S,64]; blockIdx.z selects which of Q/K/V projection to do.
// 128x128 block tile, BK=16, 256 threads, 8x8 microtile per thread.
// ---------------------------------------------------------------------------
#define PBM 128
#define PBN 128
#define PBK 16

__global__ __launch_bounds__(256, 2)
void proj_kernel(const float* __restrict__ Xq, const float* __restrict__ Xk,
                 const float* __restrict__ Xv,
                 const float* __restrict__ Wq, const float* __restrict__ Wk,
                 const float* __restrict__ Wv,
                 const float* __restrict__ bq, const float* __restrict__ bk,
                 const float* __restrict__ bv)
{
    const int z = blockIdx.z;
    const float* X    = (z == 0) ? Xq : (z == 1) ? Xk : Xv;
    const float* W    = (z == 0) ? Wq : (z == 1) ? Wk : Wv;
    const float* bias = (z == 0) ? bq : (z == 1) ? bk : bv;
    float* Out        = (z == 0) ? g_q : (z == 1) ? g_k : g_v;
    const float scale = (z == 0) ? 0.125f : 1.0f;   // 1/sqrt(64) folded into q

    __shared__ float Xs[PBK][PBM];   // transposed A tile
    __shared__ float Ws[PBK][PBN];   // B tile

    const int t  = threadIdx.x;
    const int tx = t & 15;
    const int ty = t >> 4;
    const int bm = blockIdx.x * PBM;
    const int bn = blockIdx.y * PBN;

    float acc[8][8];
    #pragma unroll
    for (int i = 0; i < 8; i++)
        #pragma unroll
        for (int j = 0; j < 8; j++) acc[i][j] = 0.0f;

    for (int k0 = 0; k0 < DMODEL; k0 += PBK) {
        // load X tile (128 rows x 16 k), store transposed
        #pragma unroll
        for (int r = 0; r < 2; r++) {
            int idx = t + r * 256;            // 0..511
            int row = idx >> 2;               // 0..127
            int c4  = (idx & 3) * 4;          // 0,4,8,12
            float4 v = *(const float4*)&X[(size_t)(bm + row) * DMODEL + k0 + c4];
            Xs[c4 + 0][row] = v.x;
            Xs[c4 + 1][row] = v.y;
            Xs[c4 + 2][row] = v.z;
            Xs[c4 + 3][row] = v.w;
        }
        // load W tile (16 k x 128 n)
        #pragma unroll
        for (int r = 0; r < 2; r++) {
            int idx = t + r * 256;
            int row = idx >> 5;               // 0..15
            int c4  = (idx & 31) * 4;         // 0..124
            *(float4*)&Ws[row][c4] =
                *(const float4*)&W[(size_t)(k0 + row) * DMODEL + bn + c4];
        }
        __syncthreads();

        #pragma unroll
        for (int kk = 0; kk < PBK; kk++) {
            float a[8], b[8];
            *(float4*)&a[0] = *(float4*)&Xs[kk][ty * 8];
            *(float4*)&a[4] = *(float4*)&Xs[kk][ty * 8 + 4];
            *(float4*)&b[0] = *(float4*)&Ws[kk][tx * 8];
            *(float4*)&b[4] = *(float4*)&Ws[kk][tx * 8 + 4];
            #pragma unroll
            for (int i = 0; i < 8; i++)
                #pragma unroll
                for (int j = 0; j < 8; j++)
                    acc[i][j] += a[i] * b[j];
        }
        __syncthreads();
    }

    // epilogue: add bias, scale, scatter to [B,H,S,64]
    #pragma unroll
    for (int i = 0; i < 8; i++) {
        int m  = bm + ty * 8 + i;
        int bb = m >> 10;            // batch
        int s  = m & 1023;           // seq
        #pragma unroll
        for (int j4 = 0; j4 < 8; j4 += 4) {
            int n = bn + tx * 8 + j4;       // 8-aligned -> stays within one head
            int h = n >> 6;
            int d = n & 63;
            float4 v;
            v.x = (acc[i][j4 + 0] + bias[n + 0]) * scale;
            v.y = (acc[i][j4 + 1] + bias[n + 1]) * scale;
            v.z = (acc[i][j4 + 2] + bias[n + 2]) * scale;
            v.w = (acc[i][j4 + 3] + bias[n + 3]) * scale;
            *(float4*)&Out[((size_t)((bb * NH + h) * SS + s)) * DKV + d] = v;
        }
    }
}

// ---------------------------------------------------------------------------
// Attention: per (b,h) pair and 64-query tile, loop over 64-key tiles.
// S = exp(q @ k^T) (q pre-scaled), acc += S @ V, rowsum in registers.
// out[b,s,h*64+d] = acc / (rowsum + 1e-8).
// ---------------------------------------------------------------------------
#define LDP 68   // padded leading dim (mult of 4 -> float4-aligned, kills conflicts)

__global__ __launch_bounds__(256)
void attn_kernel(float* __restrict__ out)
{
    extern __shared__ float sm[];
    float* qs  = sm;                   // [64][LDP]  q rows x d
    float* kst = qs  + 64 * LDP;       // [64][LDP]  d x key-col (transposed)
    float* ps  = kst + 64 * LDP;       // [64][LDP]  exp(S) tile
    float* vs  = ps  + 64 * LDP;       // [64][64]   key-col x d

    const int t  = threadIdx.x;
    const int tx = t & 15;
    const int ty = t >> 4;
    const int bh = blockIdx.y;             // b*16 + h
    const int q0 = blockIdx.x * 64;

    const float* qg = g_q + (size_t)bh * SS * DKV;
    const float* kg = g_k + (size_t)bh * SS * DKV;
    const float* vg = g_v + (size_t)bh * SS * DKV;

    // load q tile: 64 rows x 64 d
    {
        int row = t >> 2;
        int c0  = (t & 3) * 16;
        #pragma unroll
        for (int u = 0; u < 4; u++) {
            *(float4*)&qs[row * LDP + c0 + u * 4] =
                *(const float4*)&qg[(size_t)(q0 + row) * DKV + c0 + u * 4];
        }
    }

    float acc[4][4];
    #pragma unroll
    for (int i = 0; i < 4; i++)
        #pragma unroll
        for (int j = 0; j < 4; j++) acc[i][j] = 0.0f;
    float lsum[4] = {0.0f, 0.0f, 0.0f, 0.0f};

    for (int kt = 0; kt < SS; kt += 64) {
        __syncthreads();   // protect kst/vs from previous iteration's readers
        // load K tile (transposed into kst) + V tile
        {
            int row = t >> 2;                 // key col 0..63
            int c0  = (t & 3) * 16;
            #pragma unroll
            for (int u = 0; u < 4; u++) {
                int d = c0 + u * 4;
                float4 kv = *(const float4*)&kg[(size_t)(kt + row) * DKV + d];
                kst[(d + 0) * LDP + row] = kv.x;
                kst[(d + 1) * LDP + row] = kv.y;
                kst[(d + 2) * LDP + row] = kv.z;
                kst[(d + 3) * LDP + row] = kv.w;
                *(float4*)&vs[row * 64 + d] =
                    *(const float4*)&vg[(size_t)(kt + row) * DKV + d];
            }
        }
        __syncthreads();

        // S tile: (ty*4+i) query rows x (tx*4+j) key cols, dot over 64 d
        float s4[4][4];
        #pragma unroll
        for (int i = 0; i < 4; i++)
            #pragma unroll
            for (int j = 0; j < 4; j++) s4[i][j] = 0.0f;
        #pragma unroll
        for (int d = 0; d < 64; d++) {
            float a[4], b[4];
            #pragma unroll
            for (int i = 0; i < 4; i++) a[i] = qs[(ty * 4 + i) * LDP + d];
            *(float4*)&b[0] = *(float4*)&kst[d * LDP + tx * 4];
            #pragma unroll
            for (int i = 0; i < 4; i++)
                #pragma unroll
                for (int j = 0; j < 4; j++)
                    s4[i][j] += a[i] * b[j];
        }
        // exp and stash in shared
        #pragma unroll
        for (int i = 0; i < 4; i++) {
            float4 pv;
            pv.x = expf(s4[i][0]);
            pv.y = expf(s4[i][1]);
            pv.z = expf(s4[i][2]);
            pv.w = expf(s4[i][3]);
            *(float4*)&ps[(ty * 4 + i) * LDP + tx * 4] = pv;
        }
        __syncthreads();

        // acc += P @ V ; rowsum via the broadcast a[i] loads (every thread
        // sees all 64 key cols for its rows -> full row sum in registers)
        #pragma unroll
        for (int kc = 0; kc < 64; kc++) {
            float a[4], b[4];
            #pragma unroll
            for (int i = 0; i < 4; i++) a[i] = ps[(ty * 4 + i) * LDP + kc];
            *(float4*)&b[0] = *(float4*)&vs[kc * 64 + tx * 4];
            #pragma unroll
            for (int i = 0; i < 4; i++) {
                lsum[i] += a[i];
                #pragma unroll
                for (int j = 0; j < 4; j++)
                    acc[i][j] += a[i] * b[j];
            }
        }
    }

    // lsum counted each row's 64 cols per tile once... but note every thread
    // accumulated lsum[i] identically (broadcast), so it is the exact row sum.
    // However it was added once per kc per tile -> exactly sum over all 1024 keys.
    const int bb = bh >> 4;
    const int h  = bh & 15;
    #pragma unroll
    for (int i = 0; i < 4; i++) {
        int s = q0 + ty * 4 + i;
        float inv = 1.0f / (lsum[i] + 1e-8f);
        float4 v;
        v.x = acc[i][0] * inv;
        v.y = acc[i][1] * inv;
        v.z = acc[i][2] * inv;
        v.w = acc[i][3] * inv;
        *(float4*)&out[((size_t)(bb * SS + s)) * DMODEL + h * DKV + tx * 4] = v;
    }
}

// ---------------------------------------------------------------------------
extern "C" void kernel_launch(void* const* d_in, const int* in_sizes, int n_in,
                              void* d_out, int out_size)
{
    const float* Q  = (const float*)d_in[0];
    const float* K  = (const float*)d_in[1];
    const float* V  = (const float*)d_in[2];
    const float* Wq = (const float*)d_in[3];
    const float* bq = (const float*)d_in[4];
    const float* Wk = (const float*)d_in[5];
    const float* bk = (const float*)d_in[6];
    const float* Wv = (const float*)d_in[7];
    const float* bv = (const float*)d_in[8];
    float* out = (float*)d_out;

    const int attn_smem = (3 * 64 * LDP + 64 * 64) * (int)sizeof(float); // 68608 B
    cudaFuncSetAttribute(attn_kernel,
                         cudaFuncAttributeMaxDynamicSharedMemorySize, attn_smem);

    dim3 pg(MTOT / PBM, DMODEL / PBN, 3);   // 64 x 8 x 3
    proj_kernel<<<pg, 256>>>(Q, K, V, Wq, Wk, Wv, bq, bk, bv);

    dim3 ag(SS / 64, BB * NH);              // 16 x 128
    attn_kernel<<<ag, 256, attn_smem>>>(out);
}

// round 3
// speedup vs baseline: 1.4392x; 1.4392x over previous
#include <cuda_runtime.h>
#include <cuda_bf16.h>
#include <cstdint>

#define BB 8
#define SS 1024
#define NH 16
#define DKV 64
#define DMODEL 1024
#define MTOT (BB*SS)

// scratch: q,k,v in [B,H,S,64] layout, fp32 (q pre-scaled by 1/8)
__device__ float g_q[BB*NH*SS*DKV];
__device__ float g_k[BB*NH*SS*DKV];
__device__ float g_v[BB*NH*SS*DKV];

// bf16 hi/lo splits of X inputs and transposed weights [n][k]
__device__ __nv_bfloat16 g_xhi[3][MTOT*DMODEL];
__device__ __nv_bfloat16 g_xlo[3][MTOT*DMODEL];
__device__ __nv_bfloat16 g_wthi[3][DMODEL*DMODEL];
__device__ __nv_bfloat16 g_wtlo[3][DMODEL*DMODEL];

static __device__ __forceinline__ uint32_t s2u(const void* p) {
    uint32_t a;
    asm("{ .reg .u64 t; cvta.to.shared.u64 t, %1; cvt.u32.u64 %0, t; }"
        : "=r"(a) : "l"(p));
    return a;
}

static __device__ __forceinline__ void cp16(uint32_t s, const void* g) {
    asm volatile("cp.async.cg.shared.global [%0], [%1], 16;" :: "r"(s), "l"(g));
}
#define CP_COMMIT() asm volatile("cp.async.commit_group;" ::: "memory")
#define CP_WAIT1()  asm volatile("cp.async.wait_group 1;" ::: "memory")

#define LDSM4(r, addr) \
    asm volatile("ldmatrix.sync.aligned.m8n8.x4.shared.b16 {%0,%1,%2,%3}, [%4];" \
        : "=r"((r)[0]), "=r"((r)[1]), "=r"((r)[2]), "=r"((r)[3]) : "r"(addr))

#define MMA16816(d, a, b) \
    asm volatile("mma.sync.aligned.m16n8k16.row.col.f32.bf16.bf16.f32 " \
        "{%0,%1,%2,%3}, {%4,%5,%6,%7}, {%8,%9}, {%0,%1,%2,%3};" \
        : "+f"((d)[0]), "+f"((d)[1]), "+f"((d)[2]), "+f"((d)[3]) \
        : "r"((a)[0]), "r"((a)[1]), "r"((a)[2]), "r"((a)[3]), \
          "r"((b)[0]), "r"((b)[1]))

// ---------------------------------------------------------------------------
// Prep 1: X -> (hi, lo) bf16, row-major [8192, 1024]
// ---------------------------------------------------------------------------
__global__ __launch_bounds__(256)
void convert_x_kernel(const float* __restrict__ Q, const float* __restrict__ K,
                      const float* __restrict__ V)
{
    const int z = blockIdx.y;
    const float* X = (z == 0) ? Q : (z == 1) ? K : V;
    size_t i = ((size_t)blockIdx.x * 256 + threadIdx.x) * 4;
    float4 v = *(const float4*)(X + i);
    __align__(8) __nv_bfloat16 h[4], l[4];
    h[0] = __float2bfloat16(v.x); l[0] = __float2bfloat16(v.x - __bfloat162float(h[0]));
    h[1] = __float2bfloat16(v.y); l[1] = __float2bfloat16(v.y - __bfloat162float(h[1]));
    h[2] = __float2bfloat16(v.z); l[2] = __float2bfloat16(v.z - __bfloat162float(h[2]));
    h[3] = __float2bfloat16(v.w); l[3] = __float2bfloat16(v.w - __bfloat162float(h[3]));
    *(uint2*)&g_xhi[z][i] = *(uint2*)h;
    *(uint2*)&g_xlo[z][i] = *(uint2*)l;
}

// ---------------------------------------------------------------------------
// Prep 2: W [k][n] -> Wt (hi, lo) bf16 [n][k]
// ---------------------------------------------------------------------------
__global__ __launch_bounds__(256)
void conv_w_kernel(const float* __restrict__ Wq, const float* __restrict__ Wk,
                   const float* __restrict__ Wv)
{
    const int z = blockIdx.z;
    const float* W = (z == 0) ? Wq : (z == 1) ? Wk : Wv;
    __shared__ float tile[32][33];
    const int tx = threadIdx.x;
    const int ty = threadIdx.y;
    const int n0 = blockIdx.x * 32;
    const int k0 = blockIdx.y * 32;
    #pragma unroll
    for (int i = 0; i < 4; i++)
        tile[ty + i * 8][tx] = W[(size_t)(k0 + ty + i * 8) * DMODEL + n0 + tx];
    __syncthreads();
    #pragma unroll
    for (int i = 0; i < 4; i++) {
        int n = ty + i * 8;
        float x = tile[tx][n];
        __nv_bfloat16 h = __float2bfloat16(x);
        __nv_bfloat16 l = __float2bfloat16(x - __bfloat162float(h));
        size_t o = (size_t)(n0 + n) * DMODEL + k0 + tx;
        g_wthi[z][o] = h;
        g_wtlo[z][o] = l;
    }
}

// ---------------------------------------------------------------------------
// mma.sync bf16x3 projection GEMM: Out[m,n] = X@W + bias -> scatter [B,H,S,64]
// CTA 128x128, KC=64, double-buffered cp.async, 8 warps (warp tile 64x32).
// ---------------------------------------------------------------------------
#define PSTAGE 65536
#define PROJ_SMEM (1024 + 2 * PSTAGE)   // 132096

__global__ __launch_bounds__(256, 1)
void proj_mma_kernel(const float* __restrict__ bq, const float* __restrict__ bk,
                     const float* __restrict__ bv)
{
    extern __shared__ char sm[];
    const uint32_t sb = s2u(sm);
    const int t    = threadIdx.x;
    const int wid  = t >> 5;
    const int lane = t & 31;
    const int bm   = blockIdx.x * 128;
    const int bn   = blockIdx.y * 128;
    const int z    = blockIdx.z;

    const float* bias = (z == 0) ? bq : (z == 1) ? bk : bv;
    float* Out        = (z == 0) ? g_q : (z == 1) ? g_k : g_v;
    const float scale = (z == 0) ? 0.125f : 1.0f;
    const __nv_bfloat16* Xh = g_xhi[z];
    const __nv_bfloat16* Xl = g_xlo[z];
    const __nv_bfloat16* Wh = g_wthi[z];
    const __nv_bfloat16* Wl = g_wtlo[z];

    float* biasS = (float*)sm;
    if (t < 128) biasS[t] = bias[bn + t];

    const int wm = wid >> 2;    // 0..1 : m offset 64*wm
    const int wn = wid & 3;     // 0..3 : n offset 32*wn

    float acc[4][4][4];
    #pragma unroll
    for (int i = 0; i < 4; i++)
        #pragma unroll
        for (int j = 0; j < 4; j++)
            #pragma unroll
            for (int r = 0; r < 4; r++) acc[i][j][r] = 0.0f;

    // stage loader: 4 tiles of 128 rows x 128B (Ah, Al, Bh, Bl)
    #define LOAD_STAGE(c, buf) do {                                            \
        const uint32_t base_ = sb + 1024 + (buf) * PSTAGE;                     \
        const int k0_ = (c) * 64;                                              \
        _Pragma("unroll")                                                      \
        for (int r_ = 0; r_ < 4; r_++) {                                       \
            int idx_ = t + r_ * 256;                                           \
            int row_ = idx_ >> 3;                                              \
            int ch_  = idx_ & 7;                                               \
            uint32_t so_ = (uint32_t)(row_ * 128) + ((ch_ ^ (row_ & 7)) * 16); \
            size_t ga_ = (size_t)(bm + row_) * DMODEL + k0_ + ch_ * 8;         \
            size_t gb_ = (size_t)(bn + row_) * DMODEL + k0_ + ch_ * 8;         \
            cp16(base_ + so_,          Xh + ga_);                              \
            cp16(base_ + 16384 + so_,  Xl + ga_);                              \
            cp16(base_ + 32768 + so_,  Wh + gb_);                              \
            cp16(base_ + 49152 + so_,  Wl + gb_);                              \
        }                                                                      \
        CP_COMMIT();                                                           \
    } while (0)

    LOAD_STAGE(0, 0);
    LOAD_STAGE(1, 1);

    for (int c = 0; c < 16; c++) {
        CP_WAIT1();
        __syncthreads();
        const uint32_t base = sb + 1024 + (c & 1) * PSTAGE;
        #pragma unroll
        for (int ks = 0; ks < 4; ks++) {
            uint32_t aH[4][4], aL[4][4], bH[4][2], bL[4][2];
            const int chunk = 2 * ks + (lane >> 4);
            #pragma unroll
            for (int mi = 0; mi < 4; mi++) {
                int r = wm * 64 + mi * 16 + (lane & 15);
                uint32_t so = base + (uint32_t)(r * 128) + ((chunk ^ (r & 7)) * 16);
                LDSM4(aH[mi], so);
                LDSM4(aL[mi], so + 16384);
            }
            #pragma unroll
            for (int p = 0; p < 2; p++) {
                int r = wn * 32 + p * 16 + (lane & 15);
                uint32_t so = base + 32768 + (uint32_t)(r * 128) + ((chunk ^ (r & 7)) * 16);
                uint32_t q[4];
                LDSM4(q, so);
                bH[p * 2][0] = q[0]; bH[p * 2][1] = q[2];
                bH[p * 2 + 1][0] = q[1]; bH[p * 2 + 1][1] = q[3];
                LDSM4(q, so + 16384);
                bL[p * 2][0] = q[0]; bL[p * 2][1] = q[2];
                bL[p * 2 + 1][0] = q[1]; bL[p * 2 + 1][1] = q[3];
            }
            #pragma unroll
            for (int mi = 0; mi < 4; mi++)
                #pragma unroll
                for (int nf = 0; nf < 4; nf++) {
                    MMA16816(acc[mi][nf], aH[mi], bH[nf]);
                    MMA16816(acc[mi][nf], aH[mi], bL[nf]);
                    MMA16816(acc[mi][nf], aL[mi], bH[nf]);
                }
        }
        __syncthreads();
        if (c < 14) { LOAD_STAGE(c + 2, c & 1); }
        else        { CP_COMMIT(); }
    }

    // epilogue: c-frag m16n8: rows (lane>>2), (lane>>2)+8; cols (lane&3)*2, +1
    #pragma unroll
    for (int mi = 0; mi < 4; mi++) {
        #pragma unroll
        for (int nf = 0; nf < 4; nf++) {
            int nloc = wn * 32 + nf * 8 + (lane & 3) * 2;
            int n = bn + nloc;
            int h = n >> 6;
            int d = n & 63;
            float b0 = biasS[nloc], b1 = biasS[nloc + 1];
            #pragma unroll
            for (int half = 0; half < 2; half++) {
                int m = bm + wm * 64 + mi * 16 + (lane >> 2) + half * 8;
                int bb = m >> 10;
                int s  = m & 1023;
                float2 v;
                v.x = (acc[mi][nf][half * 2 + 0] + b0) * scale;
                v.y = (acc[mi][nf][half * 2 + 1] + b1) * scale;
                *(float2*)&Out[((size_t)(bb * NH + h) * SS + s) * DKV + d] = v;
            }
        }
    }
}

// ---------------------------------------------------------------------------
// Attention: per (b,h), 128q x 128k tiles, SIMT fp32.
// QK computed transposed (st[n][m], 8x8 microtile) so P lands [key][query];
// PV uses 4x8 microtile with vectorized broadcast P loads. rowsum in regs.
// ---------------------------------------------------------------------------
#define LDT 132   // padded stride for qt/kt/ps
#define LDV 68    // padded stride for vs
// smem float offsets
#define OQT 0
#define OKT (64*LDT)
#define OPS (2*64*LDT)
#define OVS (2*64*LDT + 128*LDT)
#define ATTN_SMEM ((2*64*LDT + 128*LDT + 128*LDV) * 4)   // 169984 B

__global__ __launch_bounds__(256, 1)
void attn_kernel(float* __restrict__ out)
{
    extern __shared__ float smf[];
    float* qt = smf + OQT;   // [64 d][128 m]
    float* kt = smf + OKT;   // [64 d][128 n]
    float* ps = smf + OPS;   // [128 n][128 m]
    float* vs = smf + OVS;   // [128 n][64 dv]

    const int t   = threadIdx.x;
    const int ty  = t >> 4;      // 0..15 : key rows (8 each) in QK
    const int tx  = t & 15;      // 0..15 : query cols (8 each) in QK
    const int ty2 = t >> 3;      // 0..31 : query rows (4 each) in PV
    const int tx2 = t & 7;       // 0..7  : dv cols (8 each) in PV
    const int bh  = blockIdx.y;
    const int q0  = blockIdx.x * 128;

    const float* qg = g_q + (size_t)bh * SS * DKV;
    const float* kg = g_k + (size_t)bh * SS * DKV;
    const float* vg = g_v + (size_t)bh * SS * DKV;

    // load q tile transposed: qt[d][m]
    #pragma unroll
    for (int u = 0; u < 8; u++) {
        int idx = t + u * 256;          // 0..2047
        int m   = idx & 127;
        int dq  = (idx >> 7) << 2;
        float4 v = *(const float4*)&qg[(size_t)(q0 + m) * DKV + dq];
        qt[(dq + 0) * LDT + m] = v.x;
        qt[(dq + 1) * LDT + m] = v.y;
        qt[(dq + 2) * LDT + m] = v.z;
        qt[(dq + 3) * LDT + m] = v.w;
    }

    float acc[4][8];
    #pragma unroll
    for (int i = 0; i < 4; i++)
        #pragma unroll
        for (int j = 0; j < 8; j++) acc[i][j] = 0.0f;
    float lsum[4] = {0.0f, 0.0f, 0.0f, 0.0f};

    for (int kt0 = 0; kt0 < SS; kt0 += 128) {
        __syncthreads();
        // load K (transposed) and V tiles
        #pragma unroll
        for (int u = 0; u < 8; u++) {
            int idx = t + u * 256;
            int n   = idx & 127;
            int dq  = (idx >> 7) << 2;
            float4 kv = *(const float4*)&kg[(size_t)(kt0 + n) * DKV + dq];
            kt[(dq + 0) * LDT + n] = kv.x;
            kt[(dq + 1) * LDT + n] = kv.y;
            kt[(dq + 2) * LDT + n] = kv.z;
            kt[(dq + 3) * LDT + n] = kv.w;
            *(float4*)&vs[n * LDV + dq] =
                *(const float4*)&vg[(size_t)(kt0 + n) * DKV + dq];
        }
        __syncthreads();

        // QK transposed: st[i (key)][j (query)]
        float st[8][8];
        #pragma unroll
        for (int i = 0; i < 8; i++)
            #pragma unroll
            for (int j = 0; j < 8; j++) st[i][j] = 0.0f;
        #pragma unroll 4
        for (int d = 0; d < 64; d++) {
            float a[8], b[8];
            *(float4*)&a[0] = *(float4*)&kt[d * LDT + ty * 8];
            *(float4*)&a[4] = *(float4*)&kt[d * LDT + ty * 8 + 4];
            *(float4*)&b[0] = *(float4*)&qt[d * LDT + tx * 8];
            *(float4*)&b[4] = *(float4*)&qt[d * LDT + tx * 8 + 4];
            #pragma unroll
            for (int i = 0; i < 8; i++)
                #pragma unroll
                for (int j = 0; j < 8; j++)
                    st[i][j] += a[i] * b[j];
        }
        // exp -> ps[n][m]
        #pragma unroll
        for (int i = 0; i < 8; i++) {
            float4 p0, p1;
            p0.x = __expf(st[i][0]); p0.y = __expf(st[i][1]);
            p0.z = __expf(st[i][2]); p0.w = __expf(st[i][3]);
            p1.x = __expf(st[i][4]); p1.y = __expf(st[i][5]);
            p1.z = __expf(st[i][6]); p1.w = __expf(st[i][7]);
            *(float4*)&ps[(ty * 8 + i) * LDT + tx * 8]     = p0;
            *(float4*)&ps[(ty * 8 + i) * LDT + tx * 8 + 4] = p1;
        }
        __syncthreads();

        // PV: acc[m 4][dv 8] += P[kc][m] * V[kc][dv]; rowsum from a
        #pragma unroll 4
        for (int kc = 0; kc < 128; kc++) {
            float4 a4 = *(float4*)&ps[kc * LDT + ty2 * 4];
            float b[8];
            *(float4*)&b[0] = *(float4*)&vs[kc * LDV + tx2 * 8];
            *(float4*)&b[4] = *(float4*)&vs[kc * LDV + tx2 * 8 + 4];
            float a[4] = {a4.x, a4.y, a4.z, a4.w};
            #pragma unroll
            for (int i = 0; i < 4; i++) {
                lsum[i] += a[i];
                #pragma unroll
                for (int j = 0; j < 8; j++)
                    acc[i][j] += a[i] * b[j];
            }
        }
    }

    const int bb = bh >> 4;
    const int h  = bh & 15;
    #pragma unroll
    for (int i = 0; i < 4; i++) {
        int s = q0 + ty2 * 4 + i;
        float inv = 1.0f / (lsum[i] + 1e-8f);
        float* dst = &out[((size_t)(bb * SS + s)) * DMODEL + h * DKV + tx2 * 8];
        float4 v0, v1;
        v0.x = acc[i][0] * inv; v0.y = acc[i][1] * inv;
        v0.z = acc[i][2] * inv; v0.w = acc[i][3] * inv;
        v1.x = acc[i][4] * inv; v1.y = acc[i][5] * inv;
        v1.z = acc[i][6] * inv; v1.w = acc[i][7] * inv;
        *(float4*)&dst[0] = v0;
        *(float4*)&dst[4] = v1;
    }
}

// ---------------------------------------------------------------------------
extern "C" void kernel_launch(void* const* d_in, const int* in_sizes, int n_in,
                              void* d_out, int out_size)
{
    const float* Q  = (const float*)d_in[0];
    const float* K  = (const float*)d_in[1];
    const float* V  = (const float*)d_in[2];
    const float* Wq = (const float*)d_in[3];
    const float* bq = (const float*)d_in[4];
    const float* Wk = (const float*)d_in[5];
    const float* bk = (const float*)d_in[6];
    const float* Wv = (const float*)d_in[7];
    const float* bv = (const float*)d_in[8];
    float* out = (float*)d_out;

    cudaFuncSetAttribute(proj_mma_kernel,
                         cudaFuncAttributeMaxDynamicSharedMemorySize, PROJ_SMEM);
    cudaFuncSetAttribute(attn_kernel,
                         cudaFuncAttributeMaxDynamicSharedMemorySize, ATTN_SMEM);

    convert_x_kernel<<<dim3(MTOT * DMODEL / 1024, 3), 256>>>(Q, K, V);
    conv_w_kernel<<<dim3(32, 32, 3), dim3(32, 8)>>>(Wq, Wk, Wv);

    dim3 pg(MTOT / 128, DMODEL / 128, 3);   // 64 x 8 x 3
    proj_mma_kernel<<<pg, 256, PROJ_SMEM>>>(bq, bk, bv);

    dim3 ag(SS / 128, BB * NH);             // 8 x 128
    attn_kernel<<<ag, 256, ATTN_SMEM>>>(out);
}

// round 4
// speedup vs baseline: 1.4401x; 1.0006x over previous
#include <cuda_runtime.h>
#include <cuda_bf16.h>
#include <cstdint>

#define BB 8
#define SS 1024
#define NH 16
#define DKV 64
#define DMODEL 1024
#define MTOT (BB*SS)

// scratch: q,k,v in [B,H,S,64] layout, fp32 (q pre-scaled by 1/8)
__device__ float g_q[BB*NH*SS*DKV];
__device__ float g_k[BB*NH*SS*DKV];
__device__ float g_v[BB*NH*SS*DKV];

// bf16 hi/lo splits of X inputs and transposed weights [n][k]
__device__ __nv_bfloat16 g_xhi[3][MTOT*DMODEL];
__device__ __nv_bfloat16 g_xlo[3][MTOT*DMODEL];
__device__ __nv_bfloat16 g_wthi[3][DMODEL*DMODEL];
__device__ __nv_bfloat16 g_wtlo[3][DMODEL*DMODEL];

static __device__ __forceinline__ uint32_t s2u(const void* p) {
    uint32_t a;
    asm("{ .reg .u64 t; cvta.to.shared.u64 t, %1; cvt.u32.u64 %0, t; }"
        : "=r"(a) : "l"(p));
    return a;
}

static __device__ __forceinline__ void cp16(uint32_t s, const void* g) {
    asm volatile("cp.async.cg.shared.global [%0], [%1], 16;" :: "r"(s), "l"(g));
}
#define CP_COMMIT() asm volatile("cp.async.commit_group;" ::: "memory")
#define CP_WAIT1()  asm volatile("cp.async.wait_group 1;" ::: "memory")

#define LDSM4(r, addr) \
    asm volatile("ldmatrix.sync.aligned.m8n8.x4.shared.b16 {%0,%1,%2,%3}, [%4];" \
        : "=r"((r)[0]), "=r"((r)[1]), "=r"((r)[2]), "=r"((r)[3]) : "r"(addr))

#define MMA16816(d, a, b) \
    asm volatile("mma.sync.aligned.m16n8k16.row.col.f32.bf16.bf16.f32 " \
        "{%0,%1,%2,%3}, {%4,%5,%6,%7}, {%8,%9}, {%0,%1,%2,%3};" \
        : "+f"((d)[0]), "+f"((d)[1]), "+f"((d)[2]), "+f"((d)[3]) \
        : "r"((a)[0]), "r"((a)[1]), "r"((a)[2]), "r"((a)[3]), \
          "r"((b)[0]), "r"((b)[1]))

// ---------------------------------------------------------------------------
// Prep 1: X -> (hi, lo) bf16, row-major [8192, 1024]
// ---------------------------------------------------------------------------
__global__ __launch_bounds__(256)
void convert_x_kernel(const float* __restrict__ Q, const float* __restrict__ K,
                      const float* __restrict__ V)
{
    const int z = blockIdx.y;
    const float* X = (z == 0) ? Q : (z == 1) ? K : V;
    size_t i = ((size_t)blockIdx.x * 256 + threadIdx.x) * 4;
    float4 v = *(const float4*)(X + i);
    __align__(8) __nv_bfloat16 h[4], l[4];
    h[0] = __float2bfloat16(v.x); l[0] = __float2bfloat16(v.x - __bfloat162float(h[0]));
    h[1] = __float2bfloat16(v.y); l[1] = __float2bfloat16(v.y - __bfloat162float(h[1]));
    h[2] = __float2bfloat16(v.z); l[2] = __float2bfloat16(v.z - __bfloat162float(h[2]));
    h[3] = __float2bfloat16(v.w); l[3] = __float2bfloat16(v.w - __bfloat162float(h[3]));
    *(uint2*)&g_xhi[z][i] = *(uint2*)h;
    *(uint2*)&g_xlo[z][i] = *(uint2*)l;
}

// ---------------------------------------------------------------------------
// Prep 2: W [k][n] -> Wt (hi, lo) bf16 [n][k]
// ---------------------------------------------------------------------------
__global__ __launch_bounds__(256)
void conv_w_kernel(const float* __restrict__ Wq, const float* __restrict__ Wk,
                   const float* __restrict__ Wv)
{
    const int z = blockIdx.z;
    const float* W = (z == 0) ? Wq : (z == 1) ? Wk : Wv;
    __shared__ float tile[32][33];
    const int tx = threadIdx.x;
    const int ty = threadIdx.y;
    const int n0 = blockIdx.x * 32;
    const int k0 = blockIdx.y * 32;
    #pragma unroll
    for (int i = 0; i < 4; i++)
        tile[ty + i * 8][tx] = W[(size_t)(k0 + ty + i * 8) * DMODEL + n0 + tx];
    __syncthreads();
    #pragma unroll
    for (int i = 0; i < 4; i++) {
        int n = ty + i * 8;
        float x = tile[tx][n];
        __nv_bfloat16 h = __float2bfloat16(x);
        __nv_bfloat16 l = __float2bfloat16(x - __bfloat162float(h));
        size_t o = (size_t)(n0 + n) * DMODEL + k0 + tx;
        g_wthi[z][o] = h;
        g_wtlo[z][o] = l;
    }
}

// ---------------------------------------------------------------------------
// mma.sync bf16x3 projection GEMM: Out[m,n] = X@W + bias -> scatter [B,H,S,64]
// CTA 128x128, KC=64, double-buffered cp.async, 8 warps (warp tile 64x32).
// ---------------------------------------------------------------------------
#define PSTAGE 65536
#define PROJ_SMEM (1024 + 2 * PSTAGE)   // 132096

__global__ __launch_bounds__(256, 1)
void proj_mma_kernel(const float* __restrict__ bq, const float* __restrict__ bk,
                     const float* __restrict__ bv)
{
    extern __shared__ char sm[];
    const uint32_t sb = s2u(sm);
    const int t    = threadIdx.x;
    const int wid  = t >> 5;
    const int lane = t & 31;
    const int bm   = blockIdx.x * 128;
    const int bn   = blockIdx.y * 128;
    const int z    = blockIdx.z;

    const float* bias = (z == 0) ? bq : (z == 1) ? bk : bv;
    float* Out        = (z == 0) ? g_q : (z == 1) ? g_k : g_v;
    const float scale = (z == 0) ? 0.125f : 1.0f;
    const __nv_bfloat16* Xh = g_xhi[z];
    const __nv_bfloat16* Xl = g_xlo[z];
    const __nv_bfloat16* Wh = g_wthi[z];
    const __nv_bfloat16* Wl = g_wtlo[z];

    float* biasS = (float*)sm;
    if (t < 128) biasS[t] = bias[bn + t];

    const int wm = wid >> 2;    // 0..1 : m offset 64*wm
    const int wn = wid & 3;     // 0..3 : n offset 32*wn

    float acc[4][4][4];
    #pragma unroll
    for (int i = 0; i < 4; i++)
        #pragma unroll
        for (int j = 0; j < 4; j++)
            #pragma unroll
            for (int r = 0; r < 4; r++) acc[i][j][r] = 0.0f;

    // stage loader: 4 tiles of 128 rows x 128B (Ah, Al, Bh, Bl)
    #define LOAD_STAGE(c, buf) do {                                            \
        const uint32_t base_ = sb + 1024 + (buf) * PSTAGE;                     \
        const int k0_ = (c) * 64;                                              \
        _Pragma("unroll")                                                      \
        for (int r_ = 0; r_ < 4; r_++) {                                       \
            int idx_ = t + r_ * 256;                                           \
            int row_ = idx_ >> 3;                                              \
            int ch_  = idx_ & 7;                                               \
            uint32_t so_ = (uint32_t)(row_ * 128) + ((ch_ ^ (row_ & 7)) * 16); \
            size_t ga_ = (size_t)(bm + row_) * DMODEL + k0_ + ch_ * 8;         \
            size_t gb_ = (size_t)(bn + row_) * DMODEL + k0_ + ch_ * 8;         \
            cp16(base_ + so_,          Xh + ga_);                              \
            cp16(base_ + 16384 + so_,  Xl + ga_);                              \
            cp16(base_ + 32768 + so_,  Wh + gb_);                              \
            cp16(base_ + 49152 + so_,  Wl + gb_);                              \
        }                                                                      \
        CP_COMMIT();                                                           \
    } while (0)

    LOAD_STAGE(0, 0);
    LOAD_STAGE(1, 1);

    for (int c = 0; c < 16; c++) {
        CP_WAIT1();
        __syncthreads();
        const uint32_t base = sb + 1024 + (c & 1) * PSTAGE;
        #pragma unroll
        for (int ks = 0; ks < 4; ks++) {
            uint32_t aH[4][4], aL[4][4], bH[4][2], bL[4][2];
            const int chunk = 2 * ks + (lane >> 4);
            #pragma unroll
            for (int mi = 0; mi < 4; mi++) {
                int r = wm * 64 + mi * 16 + (lane & 15);
                uint32_t so = base + (uint32_t)(r * 128) + ((chunk ^ (r & 7)) * 16);
                LDSM4(aH[mi], so);
                LDSM4(aL[mi], so + 16384);
            }
            #pragma unroll
            for (int p = 0; p < 2; p++) {
                int r = wn * 32 + p * 16 + (lane & 15);
                uint32_t so = base + 32768 + (uint32_t)(r * 128) + ((chunk ^ (r & 7)) * 16);
                uint32_t q[4];
                LDSM4(q, so);
                bH[p * 2][0] = q[0]; bH[p * 2][1] = q[2];
                bH[p * 2 + 1][0] = q[1]; bH[p * 2 + 1][1] = q[3];
                LDSM4(q, so + 16384);
                bL[p * 2][0] = q[0]; bL[p * 2][1] = q[2];
                bL[p * 2 + 1][0] = q[1]; bL[p * 2 + 1][1] = q[3];
            }
            #pragma unroll
            for (int mi = 0; mi < 4; mi++)
                #pragma unroll
                for (int nf = 0; nf < 4; nf++) {
                    MMA16816(acc[mi][nf], aH[mi], bH[nf]);
                    MMA16816(acc[mi][nf], aH[mi], bL[nf]);
                    MMA16816(acc[mi][nf], aL[mi], bH[nf]);
                }
        }
        __syncthreads();
        if (c < 14) { LOAD_STAGE(c + 2, c & 1); }
        else        { CP_COMMIT(); }
    }

    // epilogue: c-frag m16n8: rows (lane>>2), (lane>>2)+8; cols (lane&3)*2, +1
    #pragma unroll
    for (int mi = 0; mi < 4; mi++) {
        #pragma unroll
        for (int nf = 0; nf < 4; nf++) {
            int nloc = wn * 32 + nf * 8 + (lane & 3) * 2;
            int n = bn + nloc;
            int h = n >> 6;
            int d = n & 63;
            float b0 = biasS[nloc], b1 = biasS[nloc + 1];
            #pragma unroll
            for (int half = 0; half < 2; half++) {
                int m = bm + wm * 64 + mi * 16 + (lane >> 2) + half * 8;
                int bb = m >> 10;
                int s  = m & 1023;
                float2 v;
                v.x = (acc[mi][nf][half * 2 + 0] + b0) * scale;
                v.y = (acc[mi][nf][half * 2 + 1] + b1) * scale;
                *(float2*)&Out[((size_t)(bb * NH + h) * SS + s) * DKV + d] = v;
            }
        }
    }
}

// ---------------------------------------------------------------------------
// Attention: per (b,h), 128q x 128k tiles, SIMT fp32.
// QK computed transposed (st[n][m], 8x8 microtile) so P lands [key][query];
// PV uses 4x8 microtile with vectorized broadcast P loads. rowsum in regs.
// ---------------------------------------------------------------------------
#define LDT 132   // padded stride for qt/kt/ps
#define LDV 68    // padded stride for vs
// smem float offsets
#define OQT 0
#define OKT (64*LDT)
#define OPS (2*64*LDT)
#define OVS (2*64*LDT + 128*LDT)
#define ATTN_SMEM ((2*64*LDT + 128*LDT + 128*LDV) * 4)   // 169984 B

__global__ __launch_bounds__(256, 1)
void attn_kernel(float* __restrict__ out)
{
    extern __shared__ float smf[];
    float* qt = smf + OQT;   // [64 d][128 m]
    float* kt = smf + OKT;   // [64 d][128 n]
    float* ps = smf + OPS;   // [128 n][128 m]
    float* vs = smf + OVS;   // [128 n][64 dv]

    const int t   = threadIdx.x;
    const int ty  = t >> 4;      // 0..15 : key rows (8 each) in QK
    const int tx  = t & 15;      // 0..15 : query cols (8 each) in QK
    const int ty2 = t >> 3;      // 0..31 : query rows (4 each) in PV
    const int tx2 = t & 7;       // 0..7  : dv cols (8 each) in PV
    const int bh  = blockIdx.y;
    const int q0  = blockIdx.x * 128;

    const float* qg = g_q + (size_t)bh * SS * DKV;
    const float* kg = g_k + (size_t)bh * SS * DKV;
    const float* vg = g_v + (size_t)bh * SS * DKV;

    // load q tile transposed: qt[d][m]
    #pragma unroll
    for (int u = 0; u < 8; u++) {
        int idx = t + u * 256;          // 0..2047
        int m   = idx & 127;
        int dq  = (idx >> 7) << 2;
        float4 v = *(const float4*)&qg[(size_t)(q0 + m) * DKV + dq];
        qt[(dq + 0) * LDT + m] = v.x;
        qt[(dq + 1) * LDT + m] = v.y;
        qt[(dq + 2) * LDT + m] = v.z;
        qt[(dq + 3) * LDT + m] = v.w;
    }

    float acc[4][8];
    #pragma unroll
    for (int i = 0; i < 4; i++)
        #pragma unroll
        for (int j = 0; j < 8; j++) acc[i][j] = 0.0f;
    float lsum[4] = {0.0f, 0.0f, 0.0f, 0.0f};

    for (int kt0 = 0; kt0 < SS; kt0 += 128) {
        __syncthreads();
        // load K (transposed) and V tiles
        #pragma unroll
        for (int u = 0; u < 8; u++) {
            int idx = t + u * 256;
            int n   = idx & 127;
            int dq  = (idx >> 7) << 2;
            float4 kv = *(const float4*)&kg[(size_t)(kt0 + n) * DKV + dq];
            kt[(dq + 0) * LDT + n] = kv.x;
            kt[(dq + 1) * LDT + n] = kv.y;
            kt[(dq + 2) * LDT + n] = kv.z;
            kt[(dq + 3) * LDT + n] = kv.w;
            *(float4*)&vs[n * LDV + dq] =
                *(const float4*)&vg[(size_t)(kt0 + n) * DKV + dq];
        }
        __syncthreads();

        // QK transposed: st[i (key)][j (query)]
        float st[8][8];
        #pragma unroll
        for (int i = 0; i < 8; i++)
            #pragma unroll
            for (int j = 0; j < 8; j++) st[i][j] = 0.0f;
        #pragma unroll 4
        for (int d = 0; d < 64; d++) {
            float a[8], b[8];
            *(float4*)&a[0] = *(float4*)&kt[d * LDT + ty * 8];
            *(float4*)&a[4] = *(float4*)&kt[d * LDT + ty * 8 + 4];
            *(float4*)&b[0] = *(float4*)&qt[d * LDT + tx * 8];
            *(float4*)&b[4] = *(float4*)&qt[d * LDT + tx * 8 + 4];
            #pragma unroll
            for (int i = 0; i < 8; i++)
                #pragma unroll
                for (int j = 0; j < 8; j++)
                    st[i][j] += a[i] * b[j];
        }
        // exp -> ps[n][m]
        #pragma unroll
        for (int i = 0; i < 8; i++) {
            float4 p0, p1;
            p0.x = __expf(st[i][0]); p0.y = __expf(st[i][1]);
            p0.z = __expf(st[i][2]); p0.w = __expf(st[i][3]);
            p1.x = __expf(st[i][4]); p1.y = __expf(st[i][5]);
            p1.z = __expf(st[i][6]); p1.w = __expf(st[i][7]);
            *(float4*)&ps[(ty * 8 + i) * LDT + tx * 8]     = p0;
            *(float4*)&ps[(ty * 8 + i) * LDT + tx * 8 + 4] = p1;
        }
        __syncthreads();

        // PV: acc[m 4][dv 8] += P[kc][m] * V[kc][dv]; rowsum from a
        #pragma unroll 4
        for (int kc = 0; kc < 128; kc++) {
            float4 a4 = *(float4*)&ps[kc * LDT + ty2 * 4];
            float b[8];
            *(float4*)&b[0] = *(float4*)&vs[kc * LDV + tx2 * 8];
            *(float4*)&b[4] = *(float4*)&vs[kc * LDV + tx2 * 8 + 4];
            float a[4] = {a4.x, a4.y, a4.z, a4.w};
            #pragma unroll
            for (int i = 0; i < 4; i++) {
                lsum[i] += a[i];
                #pragma unroll
                for (int j = 0; j < 8; j++)
                    acc[i][j] += a[i] * b[j];
            }
        }
    }

    const int bb = bh >> 4;
    const int h  = bh & 15;
    #pragma unroll
    for (int i = 0; i < 4; i++) {
        int s = q0 + ty2 * 4 + i;
        float inv = 1.0f / (lsum[i] + 1e-8f);
        float* dst = &out[((size_t)(bb * SS + s)) * DMODEL + h * DKV + tx2 * 8];
        float4 v0, v1;
        v0.x = acc[i][0] * inv; v0.y = acc[i][1] * inv;
        v0.z = acc[i][2] * inv; v0.w = acc[i][3] * inv;
        v1.x = acc[i][4] * inv; v1.y = acc[i][5] * inv;
        v1.z = acc[i][6] * inv; v1.w = acc[i][7] * inv;
        *(float4*)&dst[0] = v0;
        *(float4*)&dst[4] = v1;
    }
}

// ---------------------------------------------------------------------------
extern "C" void kernel_launch(void* const* d_in, const int* in_sizes, int n_in,
                              void* d_out, int out_size)
{
    const float* Q  = (const float*)d_in[0];
    const float* K  = (const float*)d_in[1];
    const float* V  = (const float*)d_in[2];
    const float* Wq = (const float*)d_in[3];
    const float* bq = (const float*)d_in[4];
    const float* Wk = (const float*)d_in[5];
    const float* bk = (const float*)d_in[6];
    const float* Wv = (const float*)d_in[7];
    const float* bv = (const float*)d_in[8];
    float* out = (float*)d_out;

    cudaFuncSetAttribute(proj_mma_kernel,
                         cudaFuncAttributeMaxDynamicSharedMemorySize, PROJ_SMEM);
    cudaFuncSetAttribute(attn_kernel,
                         cudaFuncAttributeMaxDynamicSharedMemorySize, ATTN_SMEM);

    convert_x_kernel<<<dim3(MTOT * DMODEL / 1024, 3), 256>>>(Q, K, V);
    conv_w_kernel<<<dim3(32, 32, 3), dim3(32, 8)>>>(Wq, Wk, Wv);

    dim3 pg(MTOT / 128, DMODEL / 128, 3);   // 64 x 8 x 3
    proj_mma_kernel<<<pg, 256, PROJ_SMEM>>>(bq, bk, bv);

    dim3 ag(SS / 128, BB * NH);             // 8 x 128
    attn_kernel<<<ag, 256, ATTN_SMEM>>>(out);
}

// round 5
// speedup vs baseline: 2.7198x; 1.8886x over previous
#include <cuda_runtime.h>
#include <cuda_bf16.h>
#include <cstdint>

#define BB 8
#define SS 1024
#define NH 16
#define DKV 64
#define DMODEL 1024
#define MTOT (BB*SS)

// bf16 hi/lo splits of X inputs and transposed weights [n][k]
__device__ __nv_bfloat16 g_xhi[3][MTOT*DMODEL];
__device__ __nv_bfloat16 g_xlo[3][MTOT*DMODEL];
__device__ __nv_bfloat16 g_wthi[3][DMODEL*DMODEL];
__device__ __nv_bfloat16 g_wtlo[3][DMODEL*DMODEL];

// projected q,k,v as bf16 hi/lo, [bh][s][d]; q pre-scaled by 1/8
__device__ __nv_bfloat16 g_qh[BB*NH*SS*DKV];
__device__ __nv_bfloat16 g_ql[BB*NH*SS*DKV];
__device__ __nv_bfloat16 g_kh[BB*NH*SS*DKV];
__device__ __nv_bfloat16 g_kl[BB*NH*SS*DKV];
__device__ __nv_bfloat16 g_vh[BB*NH*SS*DKV];
__device__ __nv_bfloat16 g_vl[BB*NH*SS*DKV];
// V transposed: [bh][d][s]
__device__ __nv_bfloat16 g_vth[BB*NH*DKV*SS];
__device__ __nv_bfloat16 g_vtl[BB*NH*DKV*SS];

static __device__ __forceinline__ uint32_t s2u(const void* p) {
    uint32_t a;
    asm("{ .reg .u64 t; cvta.to.shared.u64 t, %1; cvt.u32.u64 %0, t; }"
        : "=r"(a) : "l"(p));
    return a;
}

static __device__ __forceinline__ void cp16(uint32_t s, const void* g) {
    asm volatile("cp.async.cg.shared.global [%0], [%1], 16;" :: "r"(s), "l"(g));
}
#define CP_COMMIT() asm volatile("cp.async.commit_group;" ::: "memory")
#define CP_WAIT1()  asm volatile("cp.async.wait_group 1;" ::: "memory")

#define LDSM4(r, addr) \
    asm volatile("ldmatrix.sync.aligned.m8n8.x4.shared.b16 {%0,%1,%2,%3}, [%4];" \
        : "=r"((r)[0]), "=r"((r)[1]), "=r"((r)[2]), "=r"((r)[3]) : "r"(addr))

#define MMA16816(d, a, b) \
    asm volatile("mma.sync.aligned.m16n8k16.row.col.f32.bf16.bf16.f32 " \
        "{%0,%1,%2,%3}, {%4,%5,%6,%7}, {%8,%9}, {%0,%1,%2,%3};" \
        : "+f"((d)[0]), "+f"((d)[1]), "+f"((d)[2]), "+f"((d)[3]) \
        : "r"((a)[0]), "r"((a)[1]), "r"((a)[2]), "r"((a)[3]), \
          "r"((b)[0]), "r"((b)[1]))

static __device__ __forceinline__ void split_pack(float x, float y,
                                                  uint32_t& hp, uint32_t& lp) {
    __nv_bfloat16 hx = __float2bfloat16(x);
    __nv_bfloat16 hy = __float2bfloat16(y);
    __nv_bfloat16 lx = __float2bfloat16(x - __bfloat162float(hx));
    __nv_bfloat16 ly = __float2bfloat16(y - __bfloat162float(hy));
    hp = (uint32_t)__bfloat16_as_ushort(hx) | ((uint32_t)__bfloat16_as_ushort(hy) << 16);
    lp = (uint32_t)__bfloat16_as_ushort(lx) | ((uint32_t)__bfloat16_as_ushort(ly) << 16);
}

// ---------------------------------------------------------------------------
// Prep 1: X -> (hi, lo) bf16, row-major [8192, 1024]
// ---------------------------------------------------------------------------
__global__ __launch_bounds__(256)
void convert_x_kernel(const float* __restrict__ Q, const float* __restrict__ K,
                      const float* __restrict__ V)
{
    const int z = blockIdx.y;
    const float* X = (z == 0) ? Q : (z == 1) ? K : V;
    size_t i = ((size_t)blockIdx.x * 256 + threadIdx.x) * 4;
    float4 v = *(const float4*)(X + i);
    __align__(8) __nv_bfloat16 h[4], l[4];
    h[0] = __float2bfloat16(v.x); l[0] = __float2bfloat16(v.x - __bfloat162float(h[0]));
    h[1] = __float2bfloat16(v.y); l[1] = __float2bfloat16(v.y - __bfloat162float(h[1]));
    h[2] = __float2bfloat16(v.z); l[2] = __float2bfloat16(v.z - __bfloat162float(h[2]));
    h[3] = __float2bfloat16(v.w); l[3] = __float2bfloat16(v.w - __bfloat162float(h[3]));
    *(uint2*)&g_xhi[z][i] = *(uint2*)h;
    *(uint2*)&g_xlo[z][i] = *(uint2*)l;
}

// ---------------------------------------------------------------------------
// Prep 2: W [k][n] -> Wt (hi, lo) bf16 [n][k]
// ---------------------------------------------------------------------------
__global__ __launch_bounds__(256)
void conv_w_kernel(const float* __restrict__ Wq, const float* __restrict__ Wk,
                   const float* __restrict__ Wv)
{
    const int z = blockIdx.z;
    const float* W = (z == 0) ? Wq : (z == 1) ? Wk : Wv;
    __shared__ float tile[32][33];
    const int tx = threadIdx.x;
    const int ty = threadIdx.y;
    const int n0 = blockIdx.x * 32;
    const int k0 = blockIdx.y * 32;
    #pragma unroll
    for (int i = 0; i < 4; i++)
        tile[ty + i * 8][tx] = W[(size_t)(k0 + ty + i * 8) * DMODEL + n0 + tx];
    __syncthreads();
    #pragma unroll
    for (int i = 0; i < 4; i++) {
        int n = ty + i * 8;
        float x = tile[tx][n];
        __nv_bfloat16 h = __float2bfloat16(x);
        __nv_bfloat16 l = __float2bfloat16(x - __bfloat162float(h));
        size_t o = (size_t)(n0 + n) * DMODEL + k0 + tx;
        g_wthi[z][o] = h;
        g_wtlo[z][o] = l;
    }
}

// ---------------------------------------------------------------------------
// mma.sync bf16x3 projection GEMM; epilogue writes bf16 hi/lo to [bh][s][d]
// ---------------------------------------------------------------------------
#define PSTAGE 65536
#define PROJ_SMEM (1024 + 2 * PSTAGE)

__global__ __launch_bounds__(256, 1)
void proj_mma_kernel(const float* __restrict__ bq, const float* __restrict__ bk,
                     const float* __restrict__ bv)
{
    extern __shared__ char sm[];
    const uint32_t sb = s2u(sm);
    const int t    = threadIdx.x;
    const int wid  = t >> 5;
    const int lane = t & 31;
    const int bm   = blockIdx.x * 128;
    const int bn   = blockIdx.y * 128;
    const int z    = blockIdx.z;

    const float* bias = (z == 0) ? bq : (z == 1) ? bk : bv;
    const float scale = (z == 0) ? 0.125f : 1.0f;
    uint32_t* Hh = (uint32_t*)((z == 0) ? g_qh : (z == 1) ? g_kh : g_vh);
    uint32_t* Hl = (uint32_t*)((z == 0) ? g_ql : (z == 1) ? g_kl : g_vl);
    const __nv_bfloat16* Xh = g_xhi[z];
    const __nv_bfloat16* Xl = g_xlo[z];
    const __nv_bfloat16* Wh = g_wthi[z];
    const __nv_bfloat16* Wl = g_wtlo[z];

    float* biasS = (float*)sm;
    if (t < 128) biasS[t] = bias[bn + t];

    const int wm = wid >> 2;
    const int wn = wid & 3;

    float acc[4][4][4];
    #pragma unroll
    for (int i = 0; i < 4; i++)
        #pragma unroll
        for (int j = 0; j < 4; j++)
            #pragma unroll
            for (int r = 0; r < 4; r++) acc[i][j][r] = 0.0f;

    #define LOAD_STAGE(c, buf) do {                                            \
        const uint32_t base_ = sb + 1024 + (buf) * PSTAGE;                     \
        const int k0_ = (c) * 64;                                              \
        _Pragma("unroll")                                                      \
        for (int r_ = 0; r_ < 4; r_++) {                                       \
            int idx_ = t + r_ * 256;                                           \
            int row_ = idx_ >> 3;                                              \
            int ch_  = idx_ & 7;                                               \
            uint32_t so_ = (uint32_t)(row_ * 128) + ((ch_ ^ (row_ & 7)) * 16); \
            size_t ga_ = (size_t)(bm + row_) * DMODEL + k0_ + ch_ * 8;         \
            size_t gb_ = (size_t)(bn + row_) * DMODEL + k0_ + ch_ * 8;         \
            cp16(base_ + so_,          Xh + ga_);                              \
            cp16(base_ + 16384 + so_,  Xl + ga_);                              \
            cp16(base_ + 32768 + so_,  Wh + gb_);                              \
            cp16(base_ + 49152 + so_,  Wl + gb_);                              \
        }                                                                      \
        CP_COMMIT();                                                           \
    } while (0)

    LOAD_STAGE(0, 0);
    LOAD_STAGE(1, 1);

    for (int c = 0; c < 16; c++) {
        CP_WAIT1();
        __syncthreads();
        const uint32_t base = sb + 1024 + (c & 1) * PSTAGE;
        #pragma unroll
        for (int ks = 0; ks < 4; ks++) {
            uint32_t aH[4][4], aL[4][4], bH[4][2], bL[4][2];
            const int chunk = 2 * ks + (lane >> 4);
            #pragma unroll
            for (int mi = 0; mi < 4; mi++) {
                int r = wm * 64 + mi * 16 + (lane & 15);
                uint32_t so = base + (uint32_t)(r * 128) + ((chunk ^ (r & 7)) * 16);
                LDSM4(aH[mi], so);
                LDSM4(aL[mi], so + 16384);
            }
            #pragma unroll
            for (int p = 0; p < 2; p++) {
                int r = wn * 32 + p * 16 + (lane & 15);
                uint32_t so = base + 32768 + (uint32_t)(r * 128) + ((chunk ^ (r & 7)) * 16);
                uint32_t q[4];
                LDSM4(q, so);
                bH[p * 2][0] = q[0]; bH[p * 2][1] = q[2];
                bH[p * 2 + 1][0] = q[1]; bH[p * 2 + 1][1] = q[3];
                LDSM4(q, so + 16384);
                bL[p * 2][0] = q[0]; bL[p * 2][1] = q[2];
                bL[p * 2 + 1][0] = q[1]; bL[p * 2 + 1][1] = q[3];
            }
            #pragma unroll
            for (int mi = 0; mi < 4; mi++)
                #pragma unroll
                for (int nf = 0; nf < 4; nf++) {
                    MMA16816(acc[mi][nf], aH[mi], bH[nf]);
                    MMA16816(acc[mi][nf], aH[mi], bL[nf]);
                    MMA16816(acc[mi][nf], aL[mi], bH[nf]);
                }
        }
        __syncthreads();
        if (c < 14) { LOAD_STAGE(c + 2, c & 1); }
        else        { CP_COMMIT(); }
    }

    // epilogue -> bf16 hi/lo [bh][s][d], packed pair stores
    #pragma unroll
    for (int mi = 0; mi < 4; mi++) {
        #pragma unroll
        for (int nf = 0; nf < 4; nf++) {
            int nloc = wn * 32 + nf * 8 + (lane & 3) * 2;
            int n = bn + nloc;
            int h = n >> 6;
            int d = n & 63;
            float b0 = biasS[nloc], b1 = biasS[nloc + 1];
            #pragma unroll
            for (int half = 0; half < 2; half++) {
                int m = bm + wm * 64 + mi * 16 + (lane >> 2) + half * 8;
                int bb = m >> 10;
                int s  = m & 1023;
                float y0 = (acc[mi][nf][half * 2 + 0] + b0) * scale;
                float y1 = (acc[mi][nf][half * 2 + 1] + b1) * scale;
                uint32_t hp, lp;
                split_pack(y0, y1, hp, lp);
                size_t o = (((size_t)(bb * NH + h) * SS + s) * DKV + d) >> 1;
                Hh[o] = hp;
                Hl[o] = lp;
            }
        }
    }
}

// ---------------------------------------------------------------------------
// Prep 3: transpose V: [bh][s][d] -> [bh][d][s], hi and lo
// ---------------------------------------------------------------------------
__global__ __launch_bounds__(256)
void transpose_v_kernel()
{
    const int zz = blockIdx.z;
    const __nv_bfloat16* src = zz ? g_vl : g_vh;
    __nv_bfloat16* dst       = zz ? g_vtl : g_vth;
    const int bh = blockIdx.y;
    const int s0 = blockIdx.x * 64;
    __shared__ __nv_bfloat16 tile[64][72];
    const int t = threadIdx.x;
    #pragma unroll
    for (int u = 0; u < 4; u++) {
        int idx = t + u * 256;
        int r   = idx >> 4;
        int c4  = (idx & 15) * 4;
        uint2 v = *(const uint2*)&src[((size_t)bh * SS + s0 + r) * DKV + c4];
        *(uint2*)&tile[r][c4] = v;
    }
    __syncthreads();
    #pragma unroll
    for (int u = 0; u < 4; u++) {
        int idx = t + u * 256;
        int d   = idx >> 4;
        int s4  = (idx & 15) * 4;
        uint2 w;
        w.x = (uint32_t)__bfloat16_as_ushort(tile[s4 + 0][d])
            | ((uint32_t)__bfloat16_as_ushort(tile[s4 + 1][d]) << 16);
        w.y = (uint32_t)__bfloat16_as_ushort(tile[s4 + 2][d])
            | ((uint32_t)__bfloat16_as_ushort(tile[s4 + 3][d]) << 16);
        *(uint2*)&dst[((size_t)bh * DKV + d) * SS + s0 + s4] = w;
    }
}

// ---------------------------------------------------------------------------
// Attention via mma.sync bf16x3. Per (b,h): 128 queries x loop over 128-key
// tiles. 8 warps, each owns 16 query rows x all 128 keys.
// QK -> fp32 S -> exp -> rowsum (shfl) + P hi/lo packed in-register as A frags
// -> PV into fp32 ctx. out = ctx / (rowsum + 1e-8).
// ---------------------------------------------------------------------------
#define AST 65536          // stage: Kh 16K | Kl 16K | Vth 16K | Vtl 16K
#define OS0 32768          // after Qh 16K | Ql 16K
#define ATTN_SMEM (OS0 + 2 * AST)   // 163840

__global__ __launch_bounds__(256, 1)
void attn_mma_kernel(float* __restrict__ out)
{
    extern __shared__ char sm[];
    const uint32_t sb = s2u(sm);
    const int t    = threadIdx.x;
    const int w    = t >> 5;
    const int lane = t & 31;
    const int bh   = blockIdx.y;
    const int q0   = blockIdx.x * 128;

    const __nv_bfloat16* Qh = g_qh + (size_t)bh * SS * DKV;
    const __nv_bfloat16* Ql = g_ql + (size_t)bh * SS * DKV;
    const __nv_bfloat16* Kh = g_kh + (size_t)bh * SS * DKV;
    const __nv_bfloat16* Kl = g_kl + (size_t)bh * SS * DKV;
    const __nv_bfloat16* Vth = g_vth + (size_t)bh * DKV * SS;
    const __nv_bfloat16* Vtl = g_vtl + (size_t)bh * DKV * SS;

    // Q tiles (once)
    #pragma unroll
    for (int r_ = 0; r_ < 4; r_++) {
        int idx = t + r_ * 256;
        int row = idx >> 3;
        int ch  = idx & 7;
        uint32_t so = (uint32_t)(row * 128) + ((ch ^ (row & 7)) * 16);
        cp16(sb + so,          Qh + (size_t)(q0 + row) * DKV + ch * 8);
        cp16(sb + 16384 + so,  Ql + (size_t)(q0 + row) * DKV + ch * 8);
    }
    CP_COMMIT();

    #define A_LOAD_STAGE(c, stg) do {                                          \
        const uint32_t base_ = sb + OS0 + (stg) * AST;                         \
        const int kt_ = (c) * 128;                                             \
        _Pragma("unroll")                                                      \
        for (int r_ = 0; r_ < 4; r_++) {                                       \
            int idx_ = t + r_ * 256;                                           \
            int row_ = idx_ >> 3;                                              \
            int ch_  = idx_ & 7;                                               \
            uint32_t so_ = (uint32_t)(row_ * 128) + ((ch_ ^ (row_ & 7)) * 16); \
            size_t gk_ = (size_t)(kt_ + row_) * DKV + ch_ * 8;                 \
            size_t gv_ = (size_t)(row_ >> 1) * SS + kt_ + (row_ & 1) * 64 + ch_ * 8; \
            cp16(base_ + so_,          Kh  + gk_);                             \
            cp16(base_ + 16384 + so_,  Kl  + gk_);                             \
            cp16(base_ + 32768 + so_,  Vth + gv_);                             \
            cp16(base_ + 49152 + so_,  Vtl + gv_);                             \
        }                                                                      \
        CP_COMMIT();                                                           \
    } while (0)

    A_LOAD_STAGE(0, 0);
    A_LOAD_STAGE(1, 1);

    float ctx[8][4];
    #pragma unroll
    for (int f = 0; f < 8; f++)
        #pragma unroll
        for (int r = 0; r < 4; r++) ctx[f][r] = 0.0f;
    float rs0 = 0.0f, rs1 = 0.0f;

    for (int c = 0; c < 8; c++) {
        CP_WAIT1();
        __syncthreads();
        const uint32_t kbase = sb + OS0 + (c & 1) * AST;
        const uint32_t vbase = kbase + 32768;

        // ---- QK: S[16 rows][128 keys] as 16 n8-frags ----
        float S[16][4];
        #pragma unroll
        for (int f = 0; f < 16; f++)
            #pragma unroll
            for (int r = 0; r < 4; r++) S[f][r] = 0.0f;

        #pragma unroll
        for (int ks = 0; ks < 4; ks++) {
            const int chunk = 2 * ks + (lane >> 4);
            uint32_t aH[4], aL[4];
            {
                int r = w * 16 + (lane & 15);
                uint32_t so = sb + (uint32_t)(r * 128) + ((chunk ^ (r & 7)) * 16);
                LDSM4(aH, so);
                LDSM4(aL, so + 16384);
            }
            #pragma unroll
            for (int j = 0; j < 8; j++) {
                int r = j * 16 + (lane & 15);
                uint32_t so = kbase + (uint32_t)(r * 128) + ((chunk ^ (r & 7)) * 16);
                uint32_t qh[4], ql[4];
                LDSM4(qh, so);
                LDSM4(ql, so + 16384);
                uint32_t bh0[2] = {qh[0], qh[2]}, bh1[2] = {qh[1], qh[3]};
                uint32_t bl0[2] = {ql[0], ql[2]}, bl1[2] = {ql[1], ql[3]};
                MMA16816(S[2 * j],     aH, bh0);
                MMA16816(S[2 * j],     aH, bl0);
                MMA16816(S[2 * j],     aL, bh0);
                MMA16816(S[2 * j + 1], aH, bh1);
                MMA16816(S[2 * j + 1], aH, bl1);
                MMA16816(S[2 * j + 1], aL, bh1);
            }
        }

        // ---- exp + rowsum + pack P (C-frag -> A-frag identity) + PV ----
        #pragma unroll
        for (int j = 0; j < 8; j++) {
            float e0 = __expf(S[2 * j][0]),     e1 = __expf(S[2 * j][1]);
            float e2 = __expf(S[2 * j][2]),     e3 = __expf(S[2 * j][3]);
            float e4 = __expf(S[2 * j + 1][0]), e5 = __expf(S[2 * j + 1][1]);
            float e6 = __expf(S[2 * j + 1][2]), e7 = __expf(S[2 * j + 1][3]);
            rs0 += (e0 + e1) + (e4 + e5);
            rs1 += (e2 + e3) + (e6 + e7);
            uint32_t aPh[4], aPl[4];
            split_pack(e0, e1, aPh[0], aPl[0]);
            split_pack(e2, e3, aPh[1], aPl[1]);
            split_pack(e4, e5, aPh[2], aPl[2]);
            split_pack(e6, e7, aPh[3], aPl[3]);
            #pragma unroll
            for (int p = 0; p < 4; p++) {
                int pr = (p * 16 + (lane & 15)) * 2 + (j >> 2);
                int cc = (j & 3) * 2 + (lane >> 4);
                uint32_t so = vbase + (uint32_t)(pr * 128) + ((cc ^ (pr & 7)) * 16);
                uint32_t vh[4], vl[4];
                LDSM4(vh, so);
                LDSM4(vl, so + 16384);
                uint32_t bh0[2] = {vh[0], vh[2]}, bh1[2] = {vh[1], vh[3]};
                uint32_t bl0[2] = {vl[0], vl[2]}, bl1[2] = {vl[1], vl[3]};
                MMA16816(ctx[2 * p],     aPh, bh0);
                MMA16816(ctx[2 * p],     aPh, bl0);
                MMA16816(ctx[2 * p],     aPl, bh0);
                MMA16816(ctx[2 * p + 1], aPh, bh1);
                MMA16816(ctx[2 * p + 1], aPh, bl1);
                MMA16816(ctx[2 * p + 1], aPl, bh1);
            }
        }

        __syncthreads();
        if (c < 6) { A_LOAD_STAGE(c + 2, c & 1); }
        else       { CP_COMMIT(); }
    }

    // rowsum reduce across quad (lanes sharing same row)
    rs0 += __shfl_xor_sync(0xFFFFFFFF, rs0, 1);
    rs0 += __shfl_xor_sync(0xFFFFFFFF, rs0, 2);
    rs1 += __shfl_xor_sync(0xFFFFFFFF, rs1, 1);
    rs1 += __shfl_xor_sync(0xFFFFFFFF, rs1, 2);
    const float inv0 = 1.0f / (rs0 + 1e-8f);
    const float inv1 = 1.0f / (rs1 + 1e-8f);

    const int bb = bh >> 4;
    const int h  = bh & 15;
    const int sLo = q0 + w * 16 + (lane >> 2);
    #pragma unroll
    for (int f = 0; f < 8; f++) {
        int d0 = f * 8 + (lane & 3) * 2;
        float2 v0, v1;
        v0.x = ctx[f][0] * inv0; v0.y = ctx[f][1] * inv0;
        v1.x = ctx[f][2] * inv1; v1.y = ctx[f][3] * inv1;
        *(float2*)&out[((size_t)(bb * SS + sLo) * DMODEL) + h * DKV + d0]     = v0;
        *(float2*)&out[((size_t)(bb * SS + sLo + 8) * DMODEL) + h * DKV + d0] = v1;
    }
}

// ---------------------------------------------------------------------------
extern "C" void kernel_launch(void* const* d_in, const int* in_sizes, int n_in,
                              void* d_out, int out_size)
{
    const float* Q  = (const float*)d_in[0];
    const float* K  = (const float*)d_in[1];
    const float* V  = (const float*)d_in[2];
    const float* Wq = (const float*)d_in[3];
    const float* bq = (const float*)d_in[4];
    const float* Wk = (const float*)d_in[5];
    const float* bk = (const float*)d_in[6];
    const float* Wv = (const float*)d_in[7];
    const float* bv = (const float*)d_in[8];
    float* out = (float*)d_out;

    cudaFuncSetAttribute(proj_mma_kernel,
                         cudaFuncAttributeMaxDynamicSharedMemorySize, PROJ_SMEM);
    cudaFuncSetAttribute(attn_mma_kernel,
                         cudaFuncAttributeMaxDynamicSharedMemorySize, ATTN_SMEM);

    convert_x_kernel<<<dim3(MTOT * DMODEL / 1024, 3), 256>>>(Q, K, V);
    conv_w_kernel<<<dim3(32, 32, 3), dim3(32, 8)>>>(Wq, Wk, Wv);

    dim3 pg(MTOT / 128, DMODEL / 128, 3);
    proj_mma_kernel<<<pg, 256, PROJ_SMEM>>>(bq, bk, bv);

    transpose_v_kernel<<<dim3(SS / 64, BB * NH, 2), 256>>>();

    dim3 ag(SS / 128, BB * NH);
    attn_mma_kernel<<<ag, 256, ATTN_SMEM>>>(out);
}

// round 6
// speedup vs baseline: 3.8781x; 1.4259x over previous
#include <cuda_runtime.h>
#include <cuda_fp16.h>
#include <cstdint>

#define BB 8
#define SS 1024
#define NH 16
#define DKV 64
#define DMODEL 1024
#define MTOT (BB*SS)

// fp16 hi/lo splits of X inputs; weights rounded to fp16, transposed [n][k]
__device__ __half g_xhi[3][MTOT*DMODEL];
__device__ __half g_xlo[3][MTOT*DMODEL];
__device__ __half g_wt[3][DMODEL*DMODEL];

// projected tensors, [bh][s][d]; q pre-scaled by 1/8 and split hi/lo
__device__ __half g_qh[BB*NH*SS*DKV];
__device__ __half g_ql[BB*NH*SS*DKV];
__device__ __half g_kf[BB*NH*SS*DKV];
__device__ __half g_vf[BB*NH*SS*DKV];
// V transposed: [bh][d][s]
__device__ __half g_vtf[BB*NH*DKV*SS];

static __device__ __forceinline__ uint32_t s2u(const void* p) {
    uint32_t a;
    asm("{ .reg .u64 t; cvta.to.shared.u64 t, %1; cvt.u32.u64 %0, t; }"
        : "=r"(a) : "l"(p));
    return a;
}

static __device__ __forceinline__ void cp16(uint32_t s, const void* g) {
    asm volatile("cp.async.cg.shared.global [%0], [%1], 16;" :: "r"(s), "l"(g));
}
#define CP_COMMIT() asm volatile("cp.async.commit_group;" ::: "memory")
#define CP_WAIT1()  asm volatile("cp.async.wait_group 1;" ::: "memory")

#define LDSM4(r, addr) \
    asm volatile("ldmatrix.sync.aligned.m8n8.x4.shared.b16 {%0,%1,%2,%3}, [%4];" \
        : "=r"((r)[0]), "=r"((r)[1]), "=r"((r)[2]), "=r"((r)[3]) : "r"(addr))

#define MMA16816(d, a, b) \
    asm volatile("mma.sync.aligned.m16n8k16.row.col.f32.f16.f16.f32 " \
        "{%0,%1,%2,%3}, {%4,%5,%6,%7}, {%8,%9}, {%0,%1,%2,%3};" \
        : "+f"((d)[0]), "+f"((d)[1]), "+f"((d)[2]), "+f"((d)[3]) \
        : "r"((a)[0]), "r"((a)[1]), "r"((a)[2]), "r"((a)[3]), \
          "r"((b)[0]), "r"((b)[1]))

static __device__ __forceinline__ uint32_t pack2h(__half x, __half y) {
    return (uint32_t)__half_as_ushort(x) | ((uint32_t)__half_as_ushort(y) << 16);
}

static __device__ __forceinline__ void split_pack(float x, float y,
                                                  uint32_t& hp, uint32_t& lp) {
    __half hx = __float2half_rn(x);
    __half hy = __float2half_rn(y);
    __half lx = __float2half_rn(x - __half2float(hx));
    __half ly = __float2half_rn(y - __half2float(hy));
    hp = pack2h(hx, hy);
    lp = pack2h(lx, ly);
}

// ---------------------------------------------------------------------------
// Prep 1: X -> (hi, lo) fp16, row-major [8192, 1024]
// ---------------------------------------------------------------------------
__global__ __launch_bounds__(256)
void convert_x_kernel(const float* __restrict__ Q, const float* __restrict__ K,
                      const float* __restrict__ V)
{
    const int z = blockIdx.y;
    const float* X = (z == 0) ? Q : (z == 1) ? K : V;
    size_t i = ((size_t)blockIdx.x * 256 + threadIdx.x) * 4;
    float4 v = *(const float4*)(X + i);
    uint2 h, l;
    uint32_t hp, lp;
    split_pack(v.x, v.y, hp, lp); h.x = hp; l.x = lp;
    split_pack(v.z, v.w, hp, lp); h.y = hp; l.y = lp;
    *(uint2*)&g_xhi[z][i] = h;
    *(uint2*)&g_xlo[z][i] = l;
}

// ---------------------------------------------------------------------------
// Prep 2: W [k][n] -> Wt fp16 (rounded) [n][k]
// ---------------------------------------------------------------------------
__global__ __launch_bounds__(256)
void conv_w_kernel(const float* __restrict__ Wq, const float* __restrict__ Wk,
                   const float* __restrict__ Wv)
{
    const int z = blockIdx.z;
    const float* W = (z == 0) ? Wq : (z == 1) ? Wk : Wv;
    __shared__ float tile[32][33];
    const int tx = threadIdx.x;
    const int ty = threadIdx.y;
    const int n0 = blockIdx.x * 32;
    const int k0 = blockIdx.y * 32;
    #pragma unroll
    for (int i = 0; i < 4; i++)
        tile[ty + i * 8][tx] = W[(size_t)(k0 + ty + i * 8) * DMODEL + n0 + tx];
    __syncthreads();
    #pragma unroll
    for (int i = 0; i < 4; i++) {
        int n = ty + i * 8;
        g_wt[z][(size_t)(n0 + n) * DMODEL + k0 + tx] = __float2half_rn(tile[tx][n]);
    }
}

// ---------------------------------------------------------------------------
// mma.sync fp16x2 projection GEMM: Out = X@W + bias
//   X split hi/lo (A operand), W rounded fp16 (B operand): 2 MMA products.
// Epilogue: q -> hi/lo split; k, v -> single fp16. [bh][s][d] layout.
// ---------------------------------------------------------------------------
#define PSTAGE 49152   // Xh 16K | Xl 16K | W 16K
#define PROJ_SMEM (1024 + 2 * PSTAGE)

__global__ __launch_bounds__(256, 1)
void proj_mma_kernel(const float* __restrict__ bq, const float* __restrict__ bk,
                     const float* __restrict__ bv)
{
    extern __shared__ char sm[];
    const uint32_t sb = s2u(sm);
    const int t    = threadIdx.x;
    const int wid  = t >> 5;
    const int lane = t & 31;
    const int bm   = blockIdx.x * 128;
    const int bn   = blockIdx.y * 128;
    const int z    = blockIdx.z;

    const float* bias = (z == 0) ? bq : (z == 1) ? bk : bv;
    const float scale = (z == 0) ? 0.125f : 1.0f;
    const __half* Xh = g_xhi[z];
    const __half* Xl = g_xlo[z];
    const __half* Wt = g_wt[z];

    float* biasS = (float*)sm;
    if (t < 128) biasS[t] = bias[bn + t];

    const int wm = wid >> 2;
    const int wn = wid & 3;

    float acc[4][4][4];
    #pragma unroll
    for (int i = 0; i < 4; i++)
        #pragma unroll
        for (int j = 0; j < 4; j++)
            #pragma unroll
            for (int r = 0; r < 4; r++) acc[i][j][r] = 0.0f;

    #define LOAD_STAGE(c, buf) do {                                            \
        const uint32_t base_ = sb + 1024 + (buf) * PSTAGE;                     \
        const int k0_ = (c) * 64;                                              \
        _Pragma("unroll")                                                      \
        for (int r_ = 0; r_ < 4; r_++) {                                       \
            int idx_ = t + r_ * 256;                                           \
            int row_ = idx_ >> 3;                                              \
            int ch_  = idx_ & 7;                                               \
            uint32_t so_ = (uint32_t)(row_ * 128) + ((ch_ ^ (row_ & 7)) * 16); \
            size_t ga_ = (size_t)(bm + row_) * DMODEL + k0_ + ch_ * 8;         \
            size_t gb_ = (size_t)(bn + row_) * DMODEL + k0_ + ch_ * 8;         \
            cp16(base_ + so_,          Xh + ga_);                              \
            cp16(base_ + 16384 + so_,  Xl + ga_);                              \
            cp16(base_ + 32768 + so_,  Wt + gb_);                              \
        }                                                                      \
        CP_COMMIT();                                                           \
    } while (0)

    LOAD_STAGE(0, 0);
    LOAD_STAGE(1, 1);

    for (int c = 0; c < 16; c++) {
        CP_WAIT1();
        __syncthreads();
        const uint32_t base = sb + 1024 + (c & 1) * PSTAGE;
        #pragma unroll
        for (int ks = 0; ks < 4; ks++) {
            uint32_t aH[4][4], aL[4][4], bF[4][2];
            const int chunk = 2 * ks + (lane >> 4);
            #pragma unroll
            for (int mi = 0; mi < 4; mi++) {
                int r = wm * 64 + mi * 16 + (lane & 15);
                uint32_t so = base + (uint32_t)(r * 128) + ((chunk ^ (r & 7)) * 16);
                LDSM4(aH[mi], so);
                LDSM4(aL[mi], so + 16384);
            }
            #pragma unroll
            for (int p = 0; p < 2; p++) {
                int r = wn * 32 + p * 16 + (lane & 15);
                uint32_t so = base + 32768 + (uint32_t)(r * 128) + ((chunk ^ (r & 7)) * 16);
                uint32_t q[4];
                LDSM4(q, so);
                bF[p * 2][0] = q[0]; bF[p * 2][1] = q[2];
                bF[p * 2 + 1][0] = q[1]; bF[p * 2 + 1][1] = q[3];
            }
            #pragma unroll
            for (int mi = 0; mi < 4; mi++)
                #pragma unroll
                for (int nf = 0; nf < 4; nf++) {
                    MMA16816(acc[mi][nf], aH[mi], bF[nf]);
                    MMA16816(acc[mi][nf], aL[mi], bF[nf]);
                }
        }
        __syncthreads();
        if (c < 14) { LOAD_STAGE(c + 2, c & 1); }
        else        { CP_COMMIT(); }
    }

    // epilogue -> [bh][s][d]: q split hi/lo; k,v single fp16
    #pragma unroll
    for (int mi = 0; mi < 4; mi++) {
        #pragma unroll
        for (int nf = 0; nf < 4; nf++) {
            int nloc = wn * 32 + nf * 8 + (lane & 3) * 2;
            int n = bn + nloc;
            int h = n >> 6;
            int d = n & 63;
            float b0 = biasS[nloc], b1 = biasS[nloc + 1];
            #pragma unroll
            for (int half_ = 0; half_ < 2; half_++) {
                int m = bm + wm * 64 + mi * 16 + (lane >> 2) + half_ * 8;
                int bb = m >> 10;
                int s  = m & 1023;
                float y0 = (acc[mi][nf][half_ * 2 + 0] + b0) * scale;
                float y1 = (acc[mi][nf][half_ * 2 + 1] + b1) * scale;
                size_t o = (((size_t)(bb * NH + h) * SS + s) * DKV + d) >> 1;
                if (z == 0) {
                    uint32_t hp, lp;
                    split_pack(y0, y1, hp, lp);
                    ((uint32_t*)g_qh)[o] = hp;
                    ((uint32_t*)g_ql)[o] = lp;
                } else {
                    uint32_t hp = pack2h(__float2half_rn(y0), __float2half_rn(y1));
                    if (z == 1) ((uint32_t*)g_kf)[o] = hp;
                    else        ((uint32_t*)g_vf)[o] = hp;
                }
            }
        }
    }
}

// ---------------------------------------------------------------------------
// Prep 3: transpose V: [bh][s][d] -> [bh][d][s]
// ---------------------------------------------------------------------------
__global__ __launch_bounds__(256)
void transpose_v_kernel()
{
    const int bh = blockIdx.y;
    const int s0 = blockIdx.x * 64;
    __shared__ __half tile[64][72];
    const int t = threadIdx.x;
    #pragma unroll
    for (int u = 0; u < 4; u++) {
        int idx = t + u * 256;
        int r   = idx >> 4;
        int c4  = (idx & 15) * 4;
        *(uint2*)&tile[r][c4] =
            *(const uint2*)&g_vf[((size_t)bh * SS + s0 + r) * DKV + c4];
    }
    __syncthreads();
    #pragma unroll
    for (int u = 0; u < 4; u++) {
        int idx = t + u * 256;
        int d   = idx >> 4;
        int s4  = (idx & 15) * 4;
        uint2 w;
        w.x = pack2h(tile[s4 + 0][d], tile[s4 + 1][d]);
        w.y = pack2h(tile[s4 + 2][d], tile[s4 + 3][d]);
        *(uint2*)&g_vtf[((size_t)bh * DKV + d) * SS + s0 + s4] = w;
    }
}

// ---------------------------------------------------------------------------
// Attention via mma.sync fp16x2. Per (b,h): 128 queries x 128-key tiles.
// QK: Q split hi/lo x K single (2 products). exp in fp32, P split hi/lo
// in-register as A-frags, PV: P x V single (2 products). Rowsum via shfl.
// ---------------------------------------------------------------------------
#define AST 32768          // stage: K 16K | Vt 16K
#define OS0 32768          // Qh 16K | Ql 16K
#define ATTN_SMEM (OS0 + 2 * AST)   // 98304

__global__ __launch_bounds__(256, 1)
void attn_mma_kernel(float* __restrict__ out)
{
    extern __shared__ char sm[];
    const uint32_t sb = s2u(sm);
    const int t    = threadIdx.x;
    const int w    = t >> 5;
    const int lane = t & 31;
    const int bh   = blockIdx.y;
    const int q0   = blockIdx.x * 128;

    const __half* Qh  = g_qh  + (size_t)bh * SS * DKV;
    const __half* Ql  = g_ql  + (size_t)bh * SS * DKV;
    const __half* Kf  = g_kf  + (size_t)bh * SS * DKV;
    const __half* Vtf = g_vtf + (size_t)bh * DKV * SS;

    // Q tiles (once)
    #pragma unroll
    for (int r_ = 0; r_ < 4; r_++) {
        int idx = t + r_ * 256;
        int row = idx >> 3;
        int ch  = idx & 7;
        uint32_t so = (uint32_t)(row * 128) + ((ch ^ (row & 7)) * 16);
        cp16(sb + so,          Qh + (size_t)(q0 + row) * DKV + ch * 8);
        cp16(sb + 16384 + so,  Ql + (size_t)(q0 + row) * DKV + ch * 8);
    }
    CP_COMMIT();

    #define A_LOAD_STAGE(c, stg) do {                                          \
        const uint32_t base_ = sb + OS0 + (stg) * AST;                         \
        const int kt_ = (c) * 128;                                             \
        _Pragma("unroll")                                                      \
        for (int r_ = 0; r_ < 4; r_++) {                                       \
            int idx_ = t + r_ * 256;                                           \
            int row_ = idx_ >> 3;                                              \
            int ch_  = idx_ & 7;                                               \
            uint32_t so_ = (uint32_t)(row_ * 128) + ((ch_ ^ (row_ & 7)) * 16); \
            size_t gk_ = (size_t)(kt_ + row_) * DKV + ch_ * 8;                 \
            size_t gv_ = (size_t)(row_ >> 1) * SS + kt_ + (row_ & 1) * 64 + ch_ * 8; \
            cp16(base_ + so_,          Kf  + gk_);                             \
            cp16(base_ + 16384 + so_,  Vtf + gv_);                             \
        }                                                                      \
        CP_COMMIT();                                                           \
    } while (0)

    A_LOAD_STAGE(0, 0);
    A_LOAD_STAGE(1, 1);

    float ctx[8][4];
    #pragma unroll
    for (int f = 0; f < 8; f++)
        #pragma unroll
        for (int r = 0; r < 4; r++) ctx[f][r] = 0.0f;
    float rs0 = 0.0f, rs1 = 0.0f;

    for (int c = 0; c < 8; c++) {
        CP_WAIT1();
        __syncthreads();
        const uint32_t kbase = sb + OS0 + (c & 1) * AST;
        const uint32_t vbase = kbase + 16384;

        // ---- QK ----
        float S[16][4];
        #pragma unroll
        for (int f = 0; f < 16; f++)
            #pragma unroll
            for (int r = 0; r < 4; r++) S[f][r] = 0.0f;

        #pragma unroll
        for (int ks = 0; ks < 4; ks++) {
            const int chunk = 2 * ks + (lane >> 4);
            uint32_t aH[4], aL[4];
            {
                int r = w * 16 + (lane & 15);
                uint32_t so = sb + (uint32_t)(r * 128) + ((chunk ^ (r & 7)) * 16);
                LDSM4(aH, so);
                LDSM4(aL, so + 16384);
            }
            #pragma unroll
            for (int j = 0; j < 8; j++) {
                int r = j * 16 + (lane & 15);
                uint32_t so = kbase + (uint32_t)(r * 128) + ((chunk ^ (r & 7)) * 16);
                uint32_t qk[4];
                LDSM4(qk, so);
                uint32_t b0[2] = {qk[0], qk[2]}, b1[2] = {qk[1], qk[3]};
                MMA16816(S[2 * j],     aH, b0);
                MMA16816(S[2 * j],     aL, b0);
                MMA16816(S[2 * j + 1], aH, b1);
                MMA16816(S[2 * j + 1], aL, b1);
            }
        }

        // ---- exp + rowsum + P split + PV ----
        #pragma unroll
        for (int j = 0; j < 8; j++) {
            float e0 = __expf(S[2 * j][0]),     e1 = __expf(S[2 * j][1]);
            float e2 = __expf(S[2 * j][2]),     e3 = __expf(S[2 * j][3]);
            float e4 = __expf(S[2 * j + 1][0]), e5 = __expf(S[2 * j + 1][1]);
            float e6 = __expf(S[2 * j + 1][2]), e7 = __expf(S[2 * j + 1][3]);
            rs0 += (e0 + e1) + (e4 + e5);
            rs1 += (e2 + e3) + (e6 + e7);
            uint32_t aPh[4], aPl[4];
            split_pack(e0, e1, aPh[0], aPl[0]);
            split_pack(e2, e3, aPh[1], aPl[1]);
            split_pack(e4, e5, aPh[2], aPl[2]);
            split_pack(e6, e7, aPh[3], aPl[3]);
            #pragma unroll
            for (int p = 0; p < 4; p++) {
                int pr = (p * 16 + (lane & 15)) * 2 + (j >> 2);
                int cc = (j & 3) * 2 + (lane >> 4);
                uint32_t so = vbase + (uint32_t)(pr * 128) + ((cc ^ (pr & 7)) * 16);
                uint32_t vv[4];
                LDSM4(vv, so);
                uint32_t b0[2] = {vv[0], vv[2]}, b1[2] = {vv[1], vv[3]};
                MMA16816(ctx[2 * p],     aPh, b0);
                MMA16816(ctx[2 * p],     aPl, b0);
                MMA16816(ctx[2 * p + 1], aPh, b1);
                MMA16816(ctx[2 * p + 1], aPl, b1);
            }
        }

        __syncthreads();
        if (c < 6) { A_LOAD_STAGE(c + 2, c & 1); }
        else       { CP_COMMIT(); }
    }

    rs0 += __shfl_xor_sync(0xFFFFFFFF, rs0, 1);
    rs0 += __shfl_xor_sync(0xFFFFFFFF, rs0, 2);
    rs1 += __shfl_xor_sync(0xFFFFFFFF, rs1, 1);
    rs1 += __shfl_xor_sync(0xFFFFFFFF, rs1, 2);
    const float inv0 = 1.0f / (rs0 + 1e-8f);
    const float inv1 = 1.0f / (rs1 + 1e-8f);

    const int bb = bh >> 4;
    const int h  = bh & 15;
    const int sLo = q0 + w * 16 + (lane >> 2);
    #pragma unroll
    for (int f = 0; f < 8; f++) {
        int d0 = f * 8 + (lane & 3) * 2;
        float2 v0, v1;
        v0.x = ctx[f][0] * inv0; v0.y = ctx[f][1] * inv0;
        v1.x = ctx[f][2] * inv1; v1.y = ctx[f][3] * inv1;
        *(float2*)&out[((size_t)(bb * SS + sLo) * DMODEL) + h * DKV + d0]     = v0;
        *(float2*)&out[((size_t)(bb * SS + sLo + 8) * DMODEL) + h * DKV + d0] = v1;
    }
}

// ---------------------------------------------------------------------------
extern "C" void kernel_launch(void* const* d_in, const int* in_sizes, int n_in,
                              void* d_out, int out_size)
{
    const float* Q  = (const float*)d_in[0];
    const float* K  = (const float*)d_in[1];
    const float* V  = (const float*)d_in[2];
    const float* Wq = (const float*)d_in[3];
    const float* bq = (const float*)d_in[4];
    const float* Wk = (const float*)d_in[5];
    const float* bk = (const float*)d_in[6];
    const float* Wv = (const float*)d_in[7];
    const float* bv = (const float*)d_in[8];
    float* out = (float*)d_out;

    cudaFuncSetAttribute(proj_mma_kernel,
                         cudaFuncAttributeMaxDynamicSharedMemorySize, PROJ_SMEM);
    cudaFuncSetAttribute(attn_mma_kernel,
                         cudaFuncAttributeMaxDynamicSharedMemorySize, ATTN_SMEM);

    convert_x_kernel<<<dim3(MTOT * DMODEL / 1024, 3), 256>>>(Q, K, V);
    conv_w_kernel<<<dim3(32, 32, 3), dim3(32, 8)>>>(Wq, Wk, Wv);

    dim3 pg(MTOT / 128, DMODEL / 128, 3);
    proj_mma_kernel<<<pg, 256, PROJ_SMEM>>>(bq, bk, bv);

    transpose_v_kernel<<<dim3(SS / 64, BB * NH), 256>>>();

    dim3 ag(SS / 128, BB * NH);
    attn_mma_kernel<<<ag, 256, ATTN_SMEM>>>(out);
}

// round 7
// speedup vs baseline: 4.0241x; 1.0377x over previous
#include <cuda_runtime.h>
#include <cuda_fp16.h>
#include <cstdint>

#define BB 8
#define SS 1024
#define NH 16
#define DKV 64
#define DMODEL 1024
#define MTOT (BB*SS)

// fp16 hi/lo splits of X inputs; weights rounded to fp16, transposed [n][k]
__device__ __half g_xhi[3][MTOT*DMODEL];
__device__ __half g_xlo[3][MTOT*DMODEL];
__device__ __half g_wt[3][DMODEL*DMODEL];

// projected tensors, [bh][s][d]; q pre-scaled by 1/8 and split hi/lo
__device__ __half g_qh[BB*NH*SS*DKV];
__device__ __half g_ql[BB*NH*SS*DKV];
__device__ __half g_kf[BB*NH*SS*DKV];
__device__ __half g_vf[BB*NH*SS*DKV];

static __device__ __forceinline__ uint32_t s2u(const void* p) {
    uint32_t a;
    asm("{ .reg .u64 t; cvta.to.shared.u64 t, %1; cvt.u32.u64 %0, t; }"
        : "=r"(a) : "l"(p));
    return a;
}

static __device__ __forceinline__ void cp16(uint32_t s, const void* g) {
    asm volatile("cp.async.cg.shared.global [%0], [%1], 16;" :: "r"(s), "l"(g));
}
#define CP_COMMIT() asm volatile("cp.async.commit_group;" ::: "memory")
#define CP_WAIT2()  asm volatile("cp.async.wait_group 2;" ::: "memory")

#define LDSM4(r, addr) \
    asm volatile("ldmatrix.sync.aligned.m8n8.x4.shared.b16 {%0,%1,%2,%3}, [%4];" \
        : "=r"((r)[0]), "=r"((r)[1]), "=r"((r)[2]), "=r"((r)[3]) : "r"(addr))

#define LDSM4T(r, addr) \
    asm volatile("ldmatrix.sync.aligned.m8n8.x4.trans.shared.b16 {%0,%1,%2,%3}, [%4];" \
        : "=r"((r)[0]), "=r"((r)[1]), "=r"((r)[2]), "=r"((r)[3]) : "r"(addr))

#define MMA16816(d, a, b) \
    asm volatile("mma.sync.aligned.m16n8k16.row.col.f32.f16.f16.f32 " \
        "{%0,%1,%2,%3}, {%4,%5,%6,%7}, {%8,%9}, {%0,%1,%2,%3};" \
        : "+f"((d)[0]), "+f"((d)[1]), "+f"((d)[2]), "+f"((d)[3]) \
        : "r"((a)[0]), "r"((a)[1]), "r"((a)[2]), "r"((a)[3]), \
          "r"((b)[0]), "r"((b)[1]))

static __device__ __forceinline__ uint32_t pack2h(__half x, __half y) {
    return (uint32_t)__half_as_ushort(x) | ((uint32_t)__half_as_ushort(y) << 16);
}

static __device__ __forceinline__ void split_pack(float x, float y,
                                                  uint32_t& hp, uint32_t& lp) {
    __half hx = __float2half_rn(x);
    __half hy = __float2half_rn(y);
    __half lx = __float2half_rn(x - __half2float(hx));
    __half ly = __float2half_rn(y - __half2float(hy));
    hp = pack2h(hx, hy);
    lp = pack2h(lx, ly);
}

// ---------------------------------------------------------------------------
// Prep 1: X -> (hi, lo) fp16, row-major [8192, 1024]
// ---------------------------------------------------------------------------
__global__ __launch_bounds__(256)
void convert_x_kernel(const float* __restrict__ Q, const float* __restrict__ K,
                      const float* __restrict__ V)
{
    const int z = blockIdx.y;
    const float* X = (z == 0) ? Q : (z == 1) ? K : V;
    size_t i = ((size_t)blockIdx.x * 256 + threadIdx.x) * 4;
    float4 v = *(const float4*)(X + i);
    uint2 h, l;
    uint32_t hp, lp;
    split_pack(v.x, v.y, hp, lp); h.x = hp; l.x = lp;
    split_pack(v.z, v.w, hp, lp); h.y = hp; l.y = lp;
    *(uint2*)&g_xhi[z][i] = h;
    *(uint2*)&g_xlo[z][i] = l;
}

// ---------------------------------------------------------------------------
// Prep 2: W [k][n] -> Wt fp16 (rounded) [n][k]
// ---------------------------------------------------------------------------
__global__ __launch_bounds__(256)
void conv_w_kernel(const float* __restrict__ Wq, const float* __restrict__ Wk,
                   const float* __restrict__ Wv)
{
    const int z = blockIdx.z;
    const float* W = (z == 0) ? Wq : (z == 1) ? Wk : Wv;
    __shared__ float tile[32][33];
    const int tx = threadIdx.x;
    const int ty = threadIdx.y;
    const int n0 = blockIdx.x * 32;
    const int k0 = blockIdx.y * 32;
    #pragma unroll
    for (int i = 0; i < 4; i++)
        tile[ty + i * 8][tx] = W[(size_t)(k0 + ty + i * 8) * DMODEL + n0 + tx];
    __syncthreads();
    #pragma unroll
    for (int i = 0; i < 4; i++) {
        int n = ty + i * 8;
        g_wt[z][(size_t)(n0 + n) * DMODEL + k0 + tx] = __float2half_rn(tile[tx][n]);
    }
}

// ---------------------------------------------------------------------------
// mma.sync fp16x2 projection GEMM, 3-stage cp.async pipeline.
// Epilogue: q -> hi/lo split; k, v -> single fp16. [bh][s][d] layout.
// ---------------------------------------------------------------------------
#define PSTAGE 49152   // Xh 16K | Xl 16K | W 16K
#define PROJ_SMEM (1024 + 3 * PSTAGE)   // 148480

__global__ __launch_bounds__(256, 1)
void proj_mma_kernel(const float* __restrict__ bq, const float* __restrict__ bk,
                     const float* __restrict__ bv)
{
    extern __shared__ char sm[];
    const uint32_t sb = s2u(sm);
    const int t    = threadIdx.x;
    const int wid  = t >> 5;
    const int lane = t & 31;
    const int bm   = blockIdx.x * 128;
    const int bn   = blockIdx.y * 128;
    const int z    = blockIdx.z;

    const float* bias = (z == 0) ? bq : (z == 1) ? bk : bv;
    const float scale = (z == 0) ? 0.125f : 1.0f;
    const __half* Xh = g_xhi[z];
    const __half* Xl = g_xlo[z];
    const __half* Wt = g_wt[z];

    float* biasS = (float*)sm;
    if (t < 128) biasS[t] = bias[bn + t];

    const int wm = wid >> 2;
    const int wn = wid & 3;

    float acc[4][4][4];
    #pragma unroll
    for (int i = 0; i < 4; i++)
        #pragma unroll
        for (int j = 0; j < 4; j++)
            #pragma unroll
            for (int r = 0; r < 4; r++) acc[i][j][r] = 0.0f;

    #define LOAD_STAGE(c, buf) do {                                            \
        const uint32_t base_ = sb + 1024 + (buf) * PSTAGE;                     \
        const int k0_ = (c) * 64;                                              \
        _Pragma("unroll")                                                      \
        for (int r_ = 0; r_ < 4; r_++) {                                       \
            int idx_ = t + r_ * 256;                                           \
            int row_ = idx_ >> 3;                                              \
            int ch_  = idx_ & 7;                                               \
            uint32_t so_ = (uint32_t)(row_ * 128) + ((ch_ ^ (row_ & 7)) * 16); \
            size_t ga_ = (size_t)(bm + row_) * DMODEL + k0_ + ch_ * 8;         \
            size_t gb_ = (size_t)(bn + row_) * DMODEL + k0_ + ch_ * 8;         \
            cp16(base_ + so_,          Xh + ga_);                              \
            cp16(base_ + 16384 + so_,  Xl + ga_);                              \
            cp16(base_ + 32768 + so_,  Wt + gb_);                              \
        }                                                                      \
        CP_COMMIT();                                                           \
    } while (0)

    LOAD_STAGE(0, 0);
    LOAD_STAGE(1, 1);
    LOAD_STAGE(2, 2);

    for (int c = 0; c < 16; c++) {
        CP_WAIT2();
        __syncthreads();
        const int bufc = c % 3;
        const uint32_t base = sb + 1024 + bufc * PSTAGE;
        #pragma unroll
        for (int ks = 0; ks < 4; ks++) {
            uint32_t aH[4][4], aL[4][4], bF[4][2];
            const int chunk = 2 * ks + (lane >> 4);
            #pragma unroll
            for (int mi = 0; mi < 4; mi++) {
                int r = wm * 64 + mi * 16 + (lane & 15);
                uint32_t so = base + (uint32_t)(r * 128) + ((chunk ^ (r & 7)) * 16);
                LDSM4(aH[mi], so);
                LDSM4(aL[mi], so + 16384);
            }
            #pragma unroll
            for (int p = 0; p < 2; p++) {
                int r = wn * 32 + p * 16 + (lane & 15);
                uint32_t so = base + 32768 + (uint32_t)(r * 128) + ((chunk ^ (r & 7)) * 16);
                uint32_t q[4];
                LDSM4(q, so);
                bF[p * 2][0] = q[0]; bF[p * 2][1] = q[2];
                bF[p * 2 + 1][0] = q[1]; bF[p * 2 + 1][1] = q[3];
            }
            #pragma unroll
            for (int mi = 0; mi < 4; mi++)
                #pragma unroll
                for (int nf = 0; nf < 4; nf++) {
                    MMA16816(acc[mi][nf], aH[mi], bF[nf]);
                    MMA16816(acc[mi][nf], aL[mi], bF[nf]);
                }
        }
        __syncthreads();
        if (c < 13) { LOAD_STAGE(c + 3, bufc); }
        else        { CP_COMMIT(); }
    }

    // epilogue -> [bh][s][d]: q split hi/lo; k,v single fp16
    #pragma unroll
    for (int mi = 0; mi < 4; mi++) {
        #pragma unroll
        for (int nf = 0; nf < 4; nf++) {
            int nloc = wn * 32 + nf * 8 + (lane & 3) * 2;
            int n = bn + nloc;
            int h = n >> 6;
            int d = n & 63;
            float b0 = biasS[nloc], b1 = biasS[nloc + 1];
            #pragma unroll
            for (int half_ = 0; half_ < 2; half_++) {
                int m = bm + wm * 64 + mi * 16 + (lane >> 2) + half_ * 8;
                int bb = m >> 10;
                int s  = m & 1023;
                float y0 = (acc[mi][nf][half_ * 2 + 0] + b0) * scale;
                float y1 = (acc[mi][nf][half_ * 2 + 1] + b1) * scale;
                size_t o = (((size_t)(bb * NH + h) * SS + s) * DKV + d) >> 1;
                if (z == 0) {
                    uint32_t hp, lp;
                    split_pack(y0, y1, hp, lp);
                    ((uint32_t*)g_qh)[o] = hp;
                    ((uint32_t*)g_ql)[o] = lp;
                } else {
                    uint32_t hp = pack2h(__float2half_rn(y0), __float2half_rn(y1));
                    if (z == 1) ((uint32_t*)g_kf)[o] = hp;
                    else        ((uint32_t*)g_vf)[o] = hp;
                }
            }
        }
    }
}

// ---------------------------------------------------------------------------
// Attention via mma.sync fp16x2, 3-stage K/V pipeline, trans-ldmatrix V.
// QK: Q split hi/lo x K (2 products). exp fp32, P split hi/lo -> A-frags,
// PV: P x V (2 products), V B-frags via ldmatrix.trans on [s][d] tiles.
// ---------------------------------------------------------------------------
#define AST 32768          // stage: K 16K | V 16K
#define OS0 32768          // Qh 16K | Ql 16K
#define ATTN_SMEM (OS0 + 3 * AST)   // 131072

__global__ __launch_bounds__(256, 1)
void attn_mma_kernel(float* __restrict__ out)
{
    extern __shared__ char sm[];
    const uint32_t sb = s2u(sm);
    const int t    = threadIdx.x;
    const int w    = t >> 5;
    const int lane = t & 31;
    const int bh   = blockIdx.y;
    const int q0   = blockIdx.x * 128;

    const __half* Qh = g_qh + (size_t)bh * SS * DKV;
    const __half* Ql = g_ql + (size_t)bh * SS * DKV;
    const __half* Kf = g_kf + (size_t)bh * SS * DKV;
    const __half* Vf = g_vf + (size_t)bh * SS * DKV;

    // Q tiles (once) — group 0
    #pragma unroll
    for (int r_ = 0; r_ < 4; r_++) {
        int idx = t + r_ * 256;
        int row = idx >> 3;
        int ch  = idx & 7;
        uint32_t so = (uint32_t)(row * 128) + ((ch ^ (row & 7)) * 16);
        cp16(sb + so,          Qh + (size_t)(q0 + row) * DKV + ch * 8);
        cp16(sb + 16384 + so,  Ql + (size_t)(q0 + row) * DKV + ch * 8);
    }
    CP_COMMIT();

    #define A_LOAD_STAGE(c, stg) do {                                          \
        const uint32_t base_ = sb + OS0 + (stg) * AST;                         \
        const int kt_ = (c) * 128;                                             \
        _Pragma("unroll")                                                      \
        for (int r_ = 0; r_ < 4; r_++) {                                       \
            int idx_ = t + r_ * 256;                                           \
            int row_ = idx_ >> 3;                                              \
            int ch_  = idx_ & 7;                                               \
            uint32_t so_ = (uint32_t)(row_ * 128) + ((ch_ ^ (row_ & 7)) * 16); \
            size_t g_ = (size_t)(kt_ + row_) * DKV + ch_ * 8;                  \
            cp16(base_ + so_,          Kf + g_);                               \
            cp16(base_ + 16384 + so_,  Vf + g_);                               \
        }                                                                      \
        CP_COMMIT();                                                           \
    } while (0)

    A_LOAD_STAGE(0, 0);
    A_LOAD_STAGE(1, 1);
    A_LOAD_STAGE(2, 2);

    float ctx[8][4];
    #pragma unroll
    for (int f = 0; f < 8; f++)
        #pragma unroll
        for (int r = 0; r < 4; r++) ctx[f][r] = 0.0f;
    float rs0 = 0.0f, rs1 = 0.0f;

    for (int c = 0; c < 8; c++) {
        CP_WAIT2();
        __syncthreads();
        const int bufc = c % 3;
        const uint32_t kbase = sb + OS0 + bufc * AST;
        const uint32_t vbase = kbase + 16384;

        // ---- QK ----
        float S[16][4];
        #pragma unroll
        for (int f = 0; f < 16; f++)
            #pragma unroll
            for (int r = 0; r < 4; r++) S[f][r] = 0.0f;

        #pragma unroll
        for (int ks = 0; ks < 4; ks++) {
            const int chunk = 2 * ks + (lane >> 4);
            uint32_t aH[4], aL[4];
            {
                int r = w * 16 + (lane & 15);
                uint32_t so = sb + (uint32_t)(r * 128) + ((chunk ^ (r & 7)) * 16);
                LDSM4(aH, so);
                LDSM4(aL, so + 16384);
            }
            #pragma unroll
            for (int j = 0; j < 8; j++) {
                int r = j * 16 + (lane & 15);
                uint32_t so = kbase + (uint32_t)(r * 128) + ((chunk ^ (r & 7)) * 16);
                uint32_t qk[4];
                LDSM4(qk, so);
                uint32_t b0[2] = {qk[0], qk[2]}, b1[2] = {qk[1], qk[3]};
                MMA16816(S[2 * j],     aH, b0);
                MMA16816(S[2 * j],     aL, b0);
                MMA16816(S[2 * j + 1], aH, b1);
                MMA16816(S[2 * j + 1], aL, b1);
            }
        }

        // ---- exp + rowsum + P split + PV (V via trans-ldmatrix) ----
        #pragma unroll
        for (int j = 0; j < 8; j++) {
            float e0 = __expf(S[2 * j][0]),     e1 = __expf(S[2 * j][1]);
            float e2 = __expf(S[2 * j][2]),     e3 = __expf(S[2 * j][3]);
            float e4 = __expf(S[2 * j + 1][0]), e5 = __expf(S[2 * j + 1][1]);
            float e6 = __expf(S[2 * j + 1][2]), e7 = __expf(S[2 * j + 1][3]);
            rs0 += (e0 + e1) + (e4 + e5);
            rs1 += (e2 + e3) + (e6 + e7);
            uint32_t aPh[4], aPl[4];
            split_pack(e0, e1, aPh[0], aPl[0]);
            split_pack(e2, e3, aPh[1], aPl[1]);
            split_pack(e4, e5, aPh[2], aPl[2]);
            split_pack(e6, e7, aPh[3], aPl[3]);
            #pragma unroll
            for (int p = 0; p < 4; p++) {
                int r  = j * 16 + (lane & 15);
                int ch = p * 2 + (lane >> 4);
                uint32_t so = vbase + (uint32_t)(r * 128) + ((ch ^ (r & 7)) * 16);
                uint32_t vv[4];
                LDSM4T(vv, so);
                uint32_t b0[2] = {vv[0], vv[1]}, b1[2] = {vv[2], vv[3]};
                MMA16816(ctx[2 * p],     aPh, b0);
                MMA16816(ctx[2 * p],     aPl, b0);
                MMA16816(ctx[2 * p + 1], aPh, b1);
                MMA16816(ctx[2 * p + 1], aPl, b1);
            }
        }

        __syncthreads();
        if (c < 5) { A_LOAD_STAGE(c + 3, bufc); }
        else       { CP_COMMIT(); }
    }

    rs0 += __shfl_xor_sync(0xFFFFFFFF, rs0, 1);
    rs0 += __shfl_xor_sync(0xFFFFFFFF, rs0, 2);
    rs1 += __shfl_xor_sync(0xFFFFFFFF, rs1, 1);
    rs1 += __shfl_xor_sync(0xFFFFFFFF, rs1, 2);
    const float inv0 = 1.0f / (rs0 + 1e-8f);
    const float inv1 = 1.0f / (rs1 + 1e-8f);

    const int bb = bh >> 4;
    const int h  = bh & 15;
    const int sLo = q0 + w * 16 + (lane >> 2);
    #pragma unroll
    for (int f = 0; f < 8; f++) {
        int d0 = f * 8 + (lane & 3) * 2;
        float2 v0, v1;
        v0.x = ctx[f][0] * inv0; v0.y = ctx[f][1] * inv0;
        v1.x = ctx[f][2] * inv1; v1.y = ctx[f][3] * inv1;
        *(float2*)&out[((size_t)(bb * SS + sLo) * DMODEL) + h * DKV + d0]     = v0;
        *(float2*)&out[((size_t)(bb * SS + sLo + 8) * DMODEL) + h * DKV + d0] = v1;
    }
}

// ---------------------------------------------------------------------------
extern "C" void kernel_launch(void* const* d_in, const int* in_sizes, int n_in,
                              void* d_out, int out_size)
{
    const float* Q  = (const float*)d_in[0];
    const float* K  = (const float*)d_in[1];
    const float* V  = (const float*)d_in[2];
    const float* Wq = (const float*)d_in[3];
    const float* bq = (const float*)d_in[4];
    const float* Wk = (const float*)d_in[5];
    const float* bk = (const float*)d_in[6];
    const float* Wv = (const float*)d_in[7];
    const float* bv = (const float*)d_in[8];
    float* out = (float*)d_out;

    cudaFuncSetAttribute(proj_mma_kernel,
                         cudaFuncAttributeMaxDynamicSharedMemorySize, PROJ_SMEM);
    cudaFuncSetAttribute(attn_mma_kernel,
                         cudaFuncAttributeMaxDynamicSharedMemorySize, ATTN_SMEM);

    convert_x_kernel<<<dim3(MTOT * DMODEL / 1024, 3), 256>>>(Q, K, V);
    conv_w_kernel<<<dim3(32, 32, 3), dim3(32, 8)>>>(Wq, Wk, Wv);

    dim3 pg(MTOT / 128, DMODEL / 128, 3);
    proj_mma_kernel<<<pg, 256, PROJ_SMEM>>>(bq, bk, bv);

    dim3 ag(SS / 128, BB * NH);
    attn_mma_kernel<<<ag, 256, ATTN_SMEM>>>(out);
}

// round 8
// speedup vs baseline: 4.3865x; 1.0901x over previous
#include <cuda_runtime.h>
#include <cuda_fp16.h>
#include <cstdint>

#define BB 8
#define SS 1024
#define NH 16
#define DKV 64
#define DMODEL 1024
#define MTOT (BB*SS)

// fp16 hi/lo splits of X inputs; weights rounded to fp16, transposed [n][k]
__device__ __half g_xhi[3][MTOT*DMODEL];
__device__ __half g_xlo[3][MTOT*DMODEL];
__device__ __half g_wt[3][DMODEL*DMODEL];

// projected tensors, [bh][s][d]; q pre-scaled by 1/8 and split hi/lo
__device__ __half g_qh[BB*NH*SS*DKV];
__device__ __half g_ql[BB*NH*SS*DKV];
__device__ __half g_kf[BB*NH*SS*DKV];
__device__ __half g_vf[BB*NH*SS*DKV];

static __device__ __forceinline__ uint32_t s2u(const void* p) {
    uint32_t a;
    asm("{ .reg .u64 t; cvta.to.shared.u64 t, %1; cvt.u32.u64 %0, t; }"
        : "=r"(a) : "l"(p));
    return a;
}

static __device__ __forceinline__ void cp16(uint32_t s, const void* g) {
    asm volatile("cp.async.cg.shared.global [%0], [%1], 16;" :: "r"(s), "l"(g));
}
#define CP_COMMIT() asm volatile("cp.async.commit_group;" ::: "memory")
#define CP_WAIT1()  asm volatile("cp.async.wait_group 1;" ::: "memory")

#define LDSM4(r, addr) \
    asm volatile("ldmatrix.sync.aligned.m8n8.x4.shared.b16 {%0,%1,%2,%3}, [%4];" \
        : "=r"((r)[0]), "=r"((r)[1]), "=r"((r)[2]), "=r"((r)[3]) : "r"(addr))

#define LDSM4T(r, addr) \
    asm volatile("ldmatrix.sync.aligned.m8n8.x4.trans.shared.b16 {%0,%1,%2,%3}, [%4];" \
        : "=r"((r)[0]), "=r"((r)[1]), "=r"((r)[2]), "=r"((r)[3]) : "r"(addr))

#define MMA16816(d, a, b) \
    asm volatile("mma.sync.aligned.m16n8k16.row.col.f32.f16.f16.f32 " \
        "{%0,%1,%2,%3}, {%4,%5,%6,%7}, {%8,%9}, {%0,%1,%2,%3};" \
        : "+f"((d)[0]), "+f"((d)[1]), "+f"((d)[2]), "+f"((d)[3]) \
        : "r"((a)[0]), "r"((a)[1]), "r"((a)[2]), "r"((a)[3]), \
          "r"((b)[0]), "r"((b)[1]))

static __device__ __forceinline__ uint32_t pack2h(__half x, __half y) {
    return (uint32_t)__half_as_ushort(x) | ((uint32_t)__half_as_ushort(y) << 16);
}

// vectorized hi/lo split of a float pair
static __device__ __forceinline__ void split_pack2(float x, float y,
                                                   uint32_t& hp, uint32_t& lp) {
    __half2 h = __float22half2_rn(make_float2(x, y));
    float2 hb = __half22float2(h);
    __half2 l = __float22half2_rn(make_float2(x - hb.x, y - hb.y));
    hp = *(uint32_t*)&h;
    lp = *(uint32_t*)&l;
}

// ---------------------------------------------------------------------------
// Prep 1: X -> (hi, lo) fp16, row-major [8192, 1024]
// ---------------------------------------------------------------------------
__global__ __launch_bounds__(256)
void convert_x_kernel(const float* __restrict__ Q, const float* __restrict__ K,
                      const float* __restrict__ V)
{
    const int z = blockIdx.y;
    const float* X = (z == 0) ? Q : (z == 1) ? K : V;
    size_t i = ((size_t)blockIdx.x * 256 + threadIdx.x) * 4;
    float4 v = *(const float4*)(X + i);
    uint2 h, l;
    split_pack2(v.x, v.y, h.x, l.x);
    split_pack2(v.z, v.w, h.y, l.y);
    *(uint2*)&g_xhi[z][i] = h;
    *(uint2*)&g_xlo[z][i] = l;
}

// ---------------------------------------------------------------------------
// Prep 2: W [k][n] -> Wt fp16 (rounded) [n][k]
// ---------------------------------------------------------------------------
__global__ __launch_bounds__(256)
void conv_w_kernel(const float* __restrict__ Wq, const float* __restrict__ Wk,
                   const float* __restrict__ Wv)
{
    const int z = blockIdx.z;
    const float* W = (z == 0) ? Wq : (z == 1) ? Wk : Wv;
    __shared__ float tile[32][33];
    const int tx = threadIdx.x;
    const int ty = threadIdx.y;
    const int n0 = blockIdx.x * 32;
    const int k0 = blockIdx.y * 32;
    #pragma unroll
    for (int i = 0; i < 4; i++)
        tile[ty + i * 8][tx] = W[(size_t)(k0 + ty + i * 8) * DMODEL + n0 + tx];
    __syncthreads();
    #pragma unroll
    for (int i = 0; i < 4; i++) {
        int n = ty + i * 8;
        g_wt[z][(size_t)(n0 + n) * DMODEL + k0 + tx] = __float2half_rn(tile[tx][n]);
    }
}

// ---------------------------------------------------------------------------
// mma.sync fp16x2 projection GEMM, 2-stage cp.async, 2 CTAs/SM.
// ---------------------------------------------------------------------------
#define PSTAGE 49152   // Xh 16K | Xl 16K | W 16K
#define PROJ_SMEM (1024 + 2 * PSTAGE)   // 99328

__global__ __launch_bounds__(256, 2)
void proj_mma_kernel(const float* __restrict__ bq, const float* __restrict__ bk,
                     const float* __restrict__ bv)
{
    extern __shared__ char sm[];
    const uint32_t sb = s2u(sm);
    const int t    = threadIdx.x;
    const int wid  = t >> 5;
    const int lane = t & 31;
    const int bm   = blockIdx.x * 128;
    const int bn   = blockIdx.y * 128;
    const int z    = blockIdx.z;

    const float* bias = (z == 0) ? bq : (z == 1) ? bk : bv;
    const float scale = (z == 0) ? 0.125f : 1.0f;
    const __half* Xh = g_xhi[z];
    const __half* Xl = g_xlo[z];
    const __half* Wt = g_wt[z];

    float* biasS = (float*)sm;
    if (t < 128) biasS[t] = bias[bn + t];

    const int wm = wid >> 2;
    const int wn = wid & 3;

    float acc[4][4][4];
    #pragma unroll
    for (int i = 0; i < 4; i++)
        #pragma unroll
        for (int j = 0; j < 4; j++)
            #pragma unroll
            for (int r = 0; r < 4; r++) acc[i][j][r] = 0.0f;

    #define LOAD_STAGE(c, buf) do {                                            \
        const uint32_t base_ = sb + 1024 + (buf) * PSTAGE;                     \
        const int k0_ = (c) * 64;                                              \
        _Pragma("unroll")                                                      \
        for (int r_ = 0; r_ < 4; r_++) {                                       \
            int idx_ = t + r_ * 256;                                           \
            int row_ = idx_ >> 3;                                              \
            int ch_  = idx_ & 7;                                               \
            uint32_t so_ = (uint32_t)(row_ * 128) + ((ch_ ^ (row_ & 7)) * 16); \
            size_t ga_ = (size_t)(bm + row_) * DMODEL + k0_ + ch_ * 8;         \
            size_t gb_ = (size_t)(bn + row_) * DMODEL + k0_ + ch_ * 8;         \
            cp16(base_ + so_,          Xh + ga_);                              \
            cp16(base_ + 16384 + so_,  Xl + ga_);                              \
            cp16(base_ + 32768 + so_,  Wt + gb_);                              \
        }                                                                      \
        CP_COMMIT();                                                           \
    } while (0)

    LOAD_STAGE(0, 0);
    LOAD_STAGE(1, 1);

    for (int c = 0; c < 16; c++) {
        CP_WAIT1();
        __syncthreads();
        const uint32_t base = sb + 1024 + (c & 1) * PSTAGE;
        #pragma unroll
        for (int ks = 0; ks < 4; ks++) {
            uint32_t aH[4][4], aL[4][4], bF[4][2];
            const int chunk = 2 * ks + (lane >> 4);
            #pragma unroll
            for (int mi = 0; mi < 4; mi++) {
                int r = wm * 64 + mi * 16 + (lane & 15);
                uint32_t so = base + (uint32_t)(r * 128) + ((chunk ^ (r & 7)) * 16);
                LDSM4(aH[mi], so);
                LDSM4(aL[mi], so + 16384);
            }
            #pragma unroll
            for (int p = 0; p < 2; p++) {
                int r = wn * 32 + p * 16 + (lane & 15);
                uint32_t so = base + 32768 + (uint32_t)(r * 128) + ((chunk ^ (r & 7)) * 16);
                uint32_t q[4];
                LDSM4(q, so);
                bF[p * 2][0] = q[0]; bF[p * 2][1] = q[2];
                bF[p * 2 + 1][0] = q[1]; bF[p * 2 + 1][1] = q[3];
            }
            #pragma unroll
            for (int mi = 0; mi < 4; mi++)
                #pragma unroll
                for (int nf = 0; nf < 4; nf++) {
                    MMA16816(acc[mi][nf], aH[mi], bF[nf]);
                    MMA16816(acc[mi][nf], aL[mi], bF[nf]);
                }
        }
        __syncthreads();
        if (c < 14) { LOAD_STAGE(c + 2, c & 1); }
        else        { CP_COMMIT(); }
    }

    // epilogue -> [bh][s][d]: q split hi/lo; k,v single fp16
    #pragma unroll
    for (int mi = 0; mi < 4; mi++) {
        #pragma unroll
        for (int nf = 0; nf < 4; nf++) {
            int nloc = wn * 32 + nf * 8 + (lane & 3) * 2;
            int n = bn + nloc;
            int h = n >> 6;
            int d = n & 63;
            float b0 = biasS[nloc], b1 = biasS[nloc + 1];
            #pragma unroll
            for (int half_ = 0; half_ < 2; half_++) {
                int m = bm + wm * 64 + mi * 16 + (lane >> 2) + half_ * 8;
                int bb = m >> 10;
                int s  = m & 1023;
                float y0 = (acc[mi][nf][half_ * 2 + 0] + b0) * scale;
                float y1 = (acc[mi][nf][half_ * 2 + 1] + b1) * scale;
                size_t o = (((size_t)(bb * NH + h) * SS + s) * DKV + d) >> 1;
                if (z == 0) {
                    uint32_t hp, lp;
                    split_pack2(y0, y1, hp, lp);
                    ((uint32_t*)g_qh)[o] = hp;
                    ((uint32_t*)g_ql)[o] = lp;
                } else {
                    uint32_t hp = pack2h(__float2half_rn(y0), __float2half_rn(y1));
                    if (z == 1) ((uint32_t*)g_kf)[o] = hp;
                    else        ((uint32_t*)g_vf)[o] = hp;
                }
            }
        }
    }
}

// ---------------------------------------------------------------------------
// Attention via mma.sync fp16x2, 2-stage K/V pipeline, 2 CTAs/SM.
// Each 128-key tile processed in two 64-key halves (live S halved -> <=128 regs).
// ---------------------------------------------------------------------------
#define AST 32768          // stage: K 16K | V 16K
#define OS0 32768          // Qh 16K | Ql 16K
#define ATTN_SMEM (OS0 + 2 * AST)   // 98304

__global__ __launch_bounds__(256, 2)
void attn_mma_kernel(float* __restrict__ out)
{
    extern __shared__ char sm[];
    const uint32_t sb = s2u(sm);
    const int t    = threadIdx.x;
    const int w    = t >> 5;
    const int lane = t & 31;
    const int bh   = blockIdx.y;
    const int q0   = blockIdx.x * 128;

    const __half* Qh = g_qh + (size_t)bh * SS * DKV;
    const __half* Ql = g_ql + (size_t)bh * SS * DKV;
    const __half* Kf = g_kf + (size_t)bh * SS * DKV;
    const __half* Vf = g_vf + (size_t)bh * SS * DKV;

    // Q tiles (once)
    #pragma unroll
    for (int r_ = 0; r_ < 4; r_++) {
        int idx = t + r_ * 256;
        int row = idx >> 3;
        int ch  = idx & 7;
        uint32_t so = (uint32_t)(row * 128) + ((ch ^ (row & 7)) * 16);
        cp16(sb + so,          Qh + (size_t)(q0 + row) * DKV + ch * 8);
        cp16(sb + 16384 + so,  Ql + (size_t)(q0 + row) * DKV + ch * 8);
    }
    CP_COMMIT();

    #define A_LOAD_STAGE(c, stg) do {                                          \
        const uint32_t base_ = sb + OS0 + (stg) * AST;                         \
        const int kt_ = (c) * 128;                                             \
        _Pragma("unroll")                                                      \
        for (int r_ = 0; r_ < 4; r_++) {                                       \
            int idx_ = t + r_ * 256;                                           \
            int row_ = idx_ >> 3;                                              \
            int ch_  = idx_ & 7;                                               \
            uint32_t so_ = (uint32_t)(row_ * 128) + ((ch_ ^ (row_ & 7)) * 16); \
            size_t g_ = (size_t)(kt_ + row_) * DKV + ch_ * 8;                  \
            cp16(base_ + so_,          Kf + g_);                               \
            cp16(base_ + 16384 + so_,  Vf + g_);                               \
        }                                                                      \
        CP_COMMIT();                                                           \
    } while (0)

    A_LOAD_STAGE(0, 0);
    A_LOAD_STAGE(1, 1);

    float ctx[8][4];
    #pragma unroll
    for (int f = 0; f < 8; f++)
        #pragma unroll
        for (int r = 0; r < 4; r++) ctx[f][r] = 0.0f;
    float rs0 = 0.0f, rs1 = 0.0f;

    for (int c = 0; c < 8; c++) {
        CP_WAIT1();
        __syncthreads();
        const uint32_t kbase = sb + OS0 + (c & 1) * AST;
        const uint32_t vbase = kbase + 16384;

        #pragma unroll
        for (int half_ = 0; half_ < 2; half_++) {
            // ---- QK for 64-key half ----
            float S[8][4];
            #pragma unroll
            for (int f = 0; f < 8; f++)
                #pragma unroll
                for (int r = 0; r < 4; r++) S[f][r] = 0.0f;

            #pragma unroll
            for (int ks = 0; ks < 4; ks++) {
                const int chunk = 2 * ks + (lane >> 4);
                uint32_t aH[4], aL[4];
                {
                    int r = w * 16 + (lane & 15);
                    uint32_t so = sb + (uint32_t)(r * 128) + ((chunk ^ (r & 7)) * 16);
                    LDSM4(aH, so);
                    LDSM4(aL, so + 16384);
                }
                #pragma unroll
                for (int j = 0; j < 4; j++) {
                    int r = half_ * 64 + j * 16 + (lane & 15);
                    uint32_t so = kbase + (uint32_t)(r * 128) + ((chunk ^ (r & 7)) * 16);
                    uint32_t qk[4];
                    LDSM4(qk, so);
                    uint32_t b0[2] = {qk[0], qk[2]}, b1[2] = {qk[1], qk[3]};
                    MMA16816(S[2 * j],     aH, b0);
                    MMA16816(S[2 * j],     aL, b0);
                    MMA16816(S[2 * j + 1], aH, b1);
                    MMA16816(S[2 * j + 1], aL, b1);
                }
            }

            // ---- exp + rowsum + P split + PV ----
            #pragma unroll
            for (int j = 0; j < 4; j++) {
                float e0 = __expf(S[2 * j][0]),     e1 = __expf(S[2 * j][1]);
                float e2 = __expf(S[2 * j][2]),     e3 = __expf(S[2 * j][3]);
                float e4 = __expf(S[2 * j + 1][0]), e5 = __expf(S[2 * j + 1][1]);
                float e6 = __expf(S[2 * j + 1][2]), e7 = __expf(S[2 * j + 1][3]);
                rs0 += (e0 + e1) + (e4 + e5);
                rs1 += (e2 + e3) + (e6 + e7);
                uint32_t aPh[4], aPl[4];
                split_pack2(e0, e1, aPh[0], aPl[0]);
                split_pack2(e2, e3, aPh[1], aPl[1]);
                split_pack2(e4, e5, aPh[2], aPl[2]);
                split_pack2(e6, e7, aPh[3], aPl[3]);
                #pragma unroll
                for (int p = 0; p < 4; p++) {
                    int r  = half_ * 64 + j * 16 + (lane & 15);
                    int ch = p * 2 + (lane >> 4);
                    uint32_t so = vbase + (uint32_t)(r * 128) + ((ch ^ (r & 7)) * 16);
                    uint32_t vv[4];
                    LDSM4T(vv, so);
                    uint32_t b0[2] = {vv[0], vv[1]}, b1[2] = {vv[2], vv[3]};
                    MMA16816(ctx[2 * p],     aPh, b0);
                    MMA16816(ctx[2 * p],     aPl, b0);
                    MMA16816(ctx[2 * p + 1], aPh, b1);
                    MMA16816(ctx[2 * p + 1], aPl, b1);
                }
            }
        }

        __syncthreads();
        if (c < 6) { A_LOAD_STAGE(c + 2, c & 1); }
        else       { CP_COMMIT(); }
    }

    rs0 += __shfl_xor_sync(0xFFFFFFFF, rs0, 1);
    rs0 += __shfl_xor_sync(0xFFFFFFFF, rs0, 2);
    rs1 += __shfl_xor_sync(0xFFFFFFFF, rs1, 1);
    rs1 += __shfl_xor_sync(0xFFFFFFFF, rs1, 2);
    const float inv0 = 1.0f / (rs0 + 1e-8f);
    const float inv1 = 1.0f / (rs1 + 1e-8f);

    const int bb = bh >> 4;
    const int h  = bh & 15;
    const int sLo = q0 + w * 16 + (lane >> 2);
    #pragma unroll
    for (int f = 0; f < 8; f++) {
        int d0 = f * 8 + (lane & 3) * 2;
        float2 v0, v1;
        v0.x = ctx[f][0] * inv0; v0.y = ctx[f][1] * inv0;
        v1.x = ctx[f][2] * inv1; v1.y = ctx[f][3] * inv1;
        *(float2*)&out[((size_t)(bb * SS + sLo) * DMODEL) + h * DKV + d0]     = v0;
        *(float2*)&out[((size_t)(bb * SS + sLo + 8) * DMODEL) + h * DKV + d0] = v1;
    }
}

// ---------------------------------------------------------------------------
extern "C" void kernel_launch(void* const* d_in, const int* in_sizes, int n_in,
                              void* d_out, int out_size)
{
    const float* Q  = (const float*)d_in[0];
    const float* K  = (const float*)d_in[1];
    const float* V  = (const float*)d_in[2];
    const float* Wq = (const float*)d_in[3];
    const float* bq = (const float*)d_in[4];
    const float* Wk = (const float*)d_in[5];
    const float* bk = (const float*)d_in[6];
    const float* Wv = (const float*)d_in[7];
    const float* bv = (const float*)d_in[8];
    float* out = (float*)d_out;

    cudaFuncSetAttribute(proj_mma_kernel,
                         cudaFuncAttributeMaxDynamicSharedMemorySize, PROJ_SMEM);
    cudaFuncSetAttribute(attn_mma_kernel,
                         cudaFuncAttributeMaxDynamicSharedMemorySize, ATTN_SMEM);

    convert_x_kernel<<<dim3(MTOT * DMODEL / 1024, 3), 256>>>(Q, K, V);
    conv_w_kernel<<<dim3(32, 32, 3), dim3(32, 8)>>>(Wq, Wk, Wv);

    dim3 pg(MTOT / 128, DMODEL / 128, 3);
    proj_mma_kernel<<<pg, 256, PROJ_SMEM>>>(bq, bk, bv);

    dim3 ag(SS / 128, BB * NH);
    attn_mma_kernel<<<ag, 256, ATTN_SMEM>>>(out);
}

// round 9
// speedup vs baseline: 4.7604x; 1.0852x over previous
#include <cuda_runtime.h>
#include <cuda_fp16.h>
#include <cstdint>

#define BB 8
#define SS 1024
#define NH 16
#define DKV 64
#define DMODEL 1024
#define MTOT (BB*SS)

// fp16 hi/lo splits of X inputs; weights rounded to fp16, transposed [n][k]
__device__ __half g_xhi[3][MTOT*DMODEL];
__device__ __half g_xlo[3][MTOT*DMODEL];
__device__ __half g_wt[3][DMODEL*DMODEL];

// projected tensors, [bh][s][d]; q pre-scaled by 1/8 and split hi/lo
__device__ __half g_qh[BB*NH*SS*DKV];
__device__ __half g_ql[BB*NH*SS*DKV];
__device__ __half g_kf[BB*NH*SS*DKV];
__device__ __half g_vf[BB*NH*SS*DKV];

static __device__ __forceinline__ uint32_t s2u(const void* p) {
    uint32_t a;
    asm("{ .reg .u64 t; cvta.to.shared.u64 t, %1; cvt.u32.u64 %0, t; }"
        : "=r"(a) : "l"(p));
    return a;
}

static __device__ __forceinline__ void cp16(uint32_t s, const void* g) {
    asm volatile("cp.async.cg.shared.global [%0], [%1], 16;" :: "r"(s), "l"(g));
}
#define CP_COMMIT() asm volatile("cp.async.commit_group;" ::: "memory")
#define CP_WAIT1()  asm volatile("cp.async.wait_group 1;" ::: "memory")

#define LDSM4(r, addr) \
    asm volatile("ldmatrix.sync.aligned.m8n8.x4.shared.b16 {%0,%1,%2,%3}, [%4];" \
        : "=r"((r)[0]), "=r"((r)[1]), "=r"((r)[2]), "=r"((r)[3]) : "r"(addr))

#define LDSM4T(r, addr) \
    asm volatile("ldmatrix.sync.aligned.m8n8.x4.trans.shared.b16 {%0,%1,%2,%3}, [%4];" \
        : "=r"((r)[0]), "=r"((r)[1]), "=r"((r)[2]), "=r"((r)[3]) : "r"(addr))

#define MMA16816(d, a, b) \
    asm volatile("mma.sync.aligned.m16n8k16.row.col.f32.f16.f16.f32 " \
        "{%0,%1,%2,%3}, {%4,%5,%6,%7}, {%8,%9}, {%0,%1,%2,%3};" \
        : "+f"((d)[0]), "+f"((d)[1]), "+f"((d)[2]), "+f"((d)[3]) \
        : "r"((a)[0]), "r"((a)[1]), "r"((a)[2]), "r"((a)[3]), \
          "r"((b)[0]), "r"((b)[1]))

static __device__ __forceinline__ uint32_t pack2h(__half x, __half y) {
    return (uint32_t)__half_as_ushort(x) | ((uint32_t)__half_as_ushort(y) << 16);
}

// vectorized hi/lo split of a float pair
static __device__ __forceinline__ void split_pack2(float x, float y,
                                                   uint32_t& hp, uint32_t& lp) {
    __half2 h = __float22half2_rn(make_float2(x, y));
    float2 hb = __half22float2(h);
    __half2 l = __float22half2_rn(make_float2(x - hb.x, y - hb.y));
    hp = *(uint32_t*)&h;
    lp = *(uint32_t*)&l;
}

static __device__ __forceinline__ uint32_t round2h(float x, float y) {
    __half2 h = __float22half2_rn(make_float2(x, y));
    return *(uint32_t*)&h;
}

// ---------------------------------------------------------------------------
// Prep 1: X -> (hi, lo) fp16, row-major [8192, 1024]
// ---------------------------------------------------------------------------
__global__ __launch_bounds__(256)
void convert_x_kernel(const float* __restrict__ Q, const float* __restrict__ K,
                      const float* __restrict__ V)
{
    const int z = blockIdx.y;
    const float* X = (z == 0) ? Q : (z == 1) ? K : V;
    size_t i = ((size_t)blockIdx.x * 256 + threadIdx.x) * 4;
    float4 v = *(const float4*)(X + i);
    uint2 h, l;
    split_pack2(v.x, v.y, h.x, l.x);
    split_pack2(v.z, v.w, h.y, l.y);
    *(uint2*)&g_xhi[z][i] = h;
    *(uint2*)&g_xlo[z][i] = l;
}

// ---------------------------------------------------------------------------
// Prep 2: W [k][n] -> Wt fp16 (rounded) [n][k]
// ---------------------------------------------------------------------------
__global__ __launch_bounds__(256)
void conv_w_kernel(const float* __restrict__ Wq, const float* __restrict__ Wk,
                   const float* __restrict__ Wv)
{
    const int z = blockIdx.z;
    const float* W = (z == 0) ? Wq : (z == 1) ? Wk : Wv;
    __shared__ float tile[32][33];
    const int tx = threadIdx.x;
    const int ty = threadIdx.y;
    const int n0 = blockIdx.x * 32;
    const int k0 = blockIdx.y * 32;
    #pragma unroll
    for (int i = 0; i < 4; i++)
        tile[ty + i * 8][tx] = W[(size_t)(k0 + ty + i * 8) * DMODEL + n0 + tx];
    __syncthreads();
    #pragma unroll
    for (int i = 0; i < 4; i++) {
        int n = ty + i * 8;
        g_wt[z][(size_t)(n0 + n) * DMODEL + k0 + tx] = __float2half_rn(tile[tx][n]);
    }
}

// ---------------------------------------------------------------------------
// mma.sync fp16x2 projection GEMM, 2-stage cp.async, 2 CTAs/SM.
// ---------------------------------------------------------------------------
#define PSTAGE 49152   // Xh 16K | Xl 16K | W 16K
#define PROJ_SMEM (1024 + 2 * PSTAGE)   // 99328

__global__ __launch_bounds__(256, 2)
void proj_mma_kernel(const float* __restrict__ bq, const float* __restrict__ bk,
                     const float* __restrict__ bv)
{
    extern __shared__ char sm[];
    const uint32_t sb = s2u(sm);
    const int t    = threadIdx.x;
    const int wid  = t >> 5;
    const int lane = t & 31;
    const int bm   = blockIdx.x * 128;
    const int bn   = blockIdx.y * 128;
    const int z    = blockIdx.z;

    const float* bias = (z == 0) ? bq : (z == 1) ? bk : bv;
    const float scale = (z == 0) ? 0.125f : 1.0f;
    const __half* Xh = g_xhi[z];
    const __half* Xl = g_xlo[z];
    const __half* Wt = g_wt[z];

    float* biasS = (float*)sm;
    if (t < 128) biasS[t] = bias[bn + t];

    const int wm = wid >> 2;
    const int wn = wid & 3;

    float acc[4][4][4];
    #pragma unroll
    for (int i = 0; i < 4; i++)
        #pragma unroll
        for (int j = 0; j < 4; j++)
            #pragma unroll
            for (int r = 0; r < 4; r++) acc[i][j][r] = 0.0f;

    #define LOAD_STAGE(c, buf) do {                                            \
        const uint32_t base_ = sb + 1024 + (buf) * PSTAGE;                     \
        const int k0_ = (c) * 64;                                              \
        _Pragma("unroll")                                                      \
        for (int r_ = 0; r_ < 4; r_++) {                                       \
            int idx_ = t + r_ * 256;                                           \
            int row_ = idx_ >> 3;                                              \
            int ch_  = idx_ & 7;                                               \
            uint32_t so_ = (uint32_t)(row_ * 128) + ((ch_ ^ (row_ & 7)) * 16); \
            size_t ga_ = (size_t)(bm + row_) * DMODEL + k0_ + ch_ * 8;         \
            size_t gb_ = (size_t)(bn + row_) * DMODEL + k0_ + ch_ * 8;         \
            cp16(base_ + so_,          Xh + ga_);                              \
            cp16(base_ + 16384 + so_,  Xl + ga_);                              \
            cp16(base_ + 32768 + so_,  Wt + gb_);                              \
        }                                                                      \
        CP_COMMIT();                                                           \
    } while (0)

    LOAD_STAGE(0, 0);
    LOAD_STAGE(1, 1);

    for (int c = 0; c < 16; c++) {
        CP_WAIT1();
        __syncthreads();
        const uint32_t base = sb + 1024 + (c & 1) * PSTAGE;
        #pragma unroll
        for (int ks = 0; ks < 4; ks++) {
            uint32_t aH[4][4], aL[4][4], bF[4][2];
            const int chunk = 2 * ks + (lane >> 4);
            #pragma unroll
            for (int mi = 0; mi < 4; mi++) {
                int r = wm * 64 + mi * 16 + (lane & 15);
                uint32_t so = base + (uint32_t)(r * 128) + ((chunk ^ (r & 7)) * 16);
                LDSM4(aH[mi], so);
                LDSM4(aL[mi], so + 16384);
            }
            #pragma unroll
            for (int p = 0; p < 2; p++) {
                int r = wn * 32 + p * 16 + (lane & 15);
                uint32_t so = base + 32768 + (uint32_t)(r * 128) + ((chunk ^ (r & 7)) * 16);
                uint32_t q[4];
                LDSM4(q, so);
                bF[p * 2][0] = q[0]; bF[p * 2][1] = q[2];
                bF[p * 2 + 1][0] = q[1]; bF[p * 2 + 1][1] = q[3];
            }
            #pragma unroll
            for (int mi = 0; mi < 4; mi++)
                #pragma unroll
                for (int nf = 0; nf < 4; nf++) {
                    MMA16816(acc[mi][nf], aH[mi], bF[nf]);
                    MMA16816(acc[mi][nf], aL[mi], bF[nf]);
                }
        }
        __syncthreads();
        if (c < 14) { LOAD_STAGE(c + 2, c & 1); }
        else        { CP_COMMIT(); }
    }

    // epilogue -> [bh][s][d]: q split hi/lo; k,v single fp16
    #pragma unroll
    for (int mi = 0; mi < 4; mi++) {
        #pragma unroll
        for (int nf = 0; nf < 4; nf++) {
            int nloc = wn * 32 + nf * 8 + (lane & 3) * 2;
            int n = bn + nloc;
            int h = n >> 6;
            int d = n & 63;
            float b0 = biasS[nloc], b1 = biasS[nloc + 1];
            #pragma unroll
            for (int half_ = 0; half_ < 2; half_++) {
                int m = bm + wm * 64 + mi * 16 + (lane >> 2) + half_ * 8;
                int bb = m >> 10;
                int s  = m & 1023;
                float y0 = (acc[mi][nf][half_ * 2 + 0] + b0) * scale;
                float y1 = (acc[mi][nf][half_ * 2 + 1] + b1) * scale;
                size_t o = (((size_t)(bb * NH + h) * SS + s) * DKV + d) >> 1;
                if (z == 0) {
                    uint32_t hp, lp;
                    split_pack2(y0, y1, hp, lp);
                    ((uint32_t*)g_qh)[o] = hp;
                    ((uint32_t*)g_ql)[o] = lp;
                } else {
                    uint32_t hp = pack2h(__float2half_rn(y0), __float2half_rn(y1));
                    if (z == 1) ((uint32_t*)g_kf)[o] = hp;
                    else        ((uint32_t*)g_vf)[o] = hp;
                }
            }
        }
    }
}

// ---------------------------------------------------------------------------
// Attention via mma.sync fp16, 2-stage K/V pipeline, 2 CTAs/SM.
// QK: Q hi/lo x K (2 products, exp-amplified so kept accurate).
// PV: P rounded to fp16, single product (linear pass-through, error ~2.4e-4).
// ---------------------------------------------------------------------------
#define AST 32768          // stage: K 16K | V 16K
#define OS0 32768          // Qh 16K | Ql 16K
#define ATTN_SMEM (OS0 + 2 * AST)   // 98304

__global__ __launch_bounds__(256, 2)
void attn_mma_kernel(float* __restrict__ out)
{
    extern __shared__ char sm[];
    const uint32_t sb = s2u(sm);
    const int t    = threadIdx.x;
    const int w    = t >> 5;
    const int lane = t & 31;
    const int bh   = blockIdx.y;
    const int q0   = blockIdx.x * 128;

    const __half* Qh = g_qh + (size_t)bh * SS * DKV;
    const __half* Ql = g_ql + (size_t)bh * SS * DKV;
    const __half* Kf = g_kf + (size_t)bh * SS * DKV;
    const __half* Vf = g_vf + (size_t)bh * SS * DKV;

    // Q tiles (once)
    #pragma unroll
    for (int r_ = 0; r_ < 4; r_++) {
        int idx = t + r_ * 256;
        int row = idx >> 3;
        int ch  = idx & 7;
        uint32_t so = (uint32_t)(row * 128) + ((ch ^ (row & 7)) * 16);
        cp16(sb + so,          Qh + (size_t)(q0 + row) * DKV + ch * 8);
        cp16(sb + 16384 + so,  Ql + (size_t)(q0 + row) * DKV + ch * 8);
    }
    CP_COMMIT();

    #define A_LOAD_STAGE(c, stg) do {                                          \
        const uint32_t base_ = sb + OS0 + (stg) * AST;                         \
        const int kt_ = (c) * 128;                                             \
        _Pragma("unroll")                                                      \
        for (int r_ = 0; r_ < 4; r_++) {                                       \
            int idx_ = t + r_ * 256;                                           \
            int row_ = idx_ >> 3;                                              \
            int ch_  = idx_ & 7;                                               \
            uint32_t so_ = (uint32_t)(row_ * 128) + ((ch_ ^ (row_ & 7)) * 16); \
            size_t g_ = (size_t)(kt_ + row_) * DKV + ch_ * 8;                  \
            cp16(base_ + so_,          Kf + g_);                               \
            cp16(base_ + 16384 + so_,  Vf + g_);                               \
        }                                                                      \
        CP_COMMIT();                                                           \
    } while (0)

    A_LOAD_STAGE(0, 0);
    A_LOAD_STAGE(1, 1);

    float ctx[8][4];
    #pragma unroll
    for (int f = 0; f < 8; f++)
        #pragma unroll
        for (int r = 0; r < 4; r++) ctx[f][r] = 0.0f;
    float rs0 = 0.0f, rs1 = 0.0f;

    for (int c = 0; c < 8; c++) {
        CP_WAIT1();
        __syncthreads();
        const uint32_t kbase = sb + OS0 + (c & 1) * AST;
        const uint32_t vbase = kbase + 16384;

        #pragma unroll
        for (int half_ = 0; half_ < 2; half_++) {
            // ---- QK for 64-key half ----
            float S[8][4];
            #pragma unroll
            for (int f = 0; f < 8; f++)
                #pragma unroll
                for (int r = 0; r < 4; r++) S[f][r] = 0.0f;

            #pragma unroll
            for (int ks = 0; ks < 4; ks++) {
                const int chunk = 2 * ks + (lane >> 4);
                uint32_t aH[4], aL[4];
                {
                    int r = w * 16 + (lane & 15);
                    uint32_t so = sb + (uint32_t)(r * 128) + ((chunk ^ (r & 7)) * 16);
                    LDSM4(aH, so);
                    LDSM4(aL, so + 16384);
                }
                #pragma unroll
                for (int j = 0; j < 4; j++) {
                    int r = half_ * 64 + j * 16 + (lane & 15);
                    uint32_t so = kbase + (uint32_t)(r * 128) + ((chunk ^ (r & 7)) * 16);
                    uint32_t qk[4];
                    LDSM4(qk, so);
                    uint32_t b0[2] = {qk[0], qk[2]}, b1[2] = {qk[1], qk[3]};
                    MMA16816(S[2 * j],     aH, b0);
                    MMA16816(S[2 * j],     aL, b0);
                    MMA16816(S[2 * j + 1], aH, b1);
                    MMA16816(S[2 * j + 1], aL, b1);
                }
            }

            // ---- exp + rowsum + P round-to-fp16 + PV (single product) ----
            #pragma unroll
            for (int j = 0; j < 4; j++) {
                float e0 = __expf(S[2 * j][0]),     e1 = __expf(S[2 * j][1]);
                float e2 = __expf(S[2 * j][2]),     e3 = __expf(S[2 * j][3]);
                float e4 = __expf(S[2 * j + 1][0]), e5 = __expf(S[2 * j + 1][1]);
                float e6 = __expf(S[2 * j + 1][2]), e7 = __expf(S[2 * j + 1][3]);
                rs0 += (e0 + e1) + (e4 + e5);
                rs1 += (e2 + e3) + (e6 + e7);
                uint32_t aP[4];
                aP[0] = round2h(e0, e1);
                aP[1] = round2h(e2, e3);
                aP[2] = round2h(e4, e5);
                aP[3] = round2h(e6, e7);
                #pragma unroll
                for (int p = 0; p < 4; p++) {
                    int r  = half_ * 64 + j * 16 + (lane & 15);
                    int ch = p * 2 + (lane >> 4);
                    uint32_t so = vbase + (uint32_t)(r * 128) + ((ch ^ (r & 7)) * 16);
                    uint32_t vv[4];
                    LDSM4T(vv, so);
                    uint32_t b0[2] = {vv[0], vv[1]}, b1[2] = {vv[2], vv[3]};
                    MMA16816(ctx[2 * p],     aP, b0);
                    MMA16816(ctx[2 * p + 1], aP, b1);
                }
            }
        }

        __syncthreads();
        if (c < 6) { A_LOAD_STAGE(c + 2, c & 1); }
        else       { CP_COMMIT(); }
    }

    rs0 += __shfl_xor_sync(0xFFFFFFFF, rs0, 1);
    rs0 += __shfl_xor_sync(0xFFFFFFFF, rs0, 2);
    rs1 += __shfl_xor_sync(0xFFFFFFFF, rs1, 1);
    rs1 += __shfl_xor_sync(0xFFFFFFFF, rs1, 2);
    const float inv0 = 1.0f / (rs0 + 1e-8f);
    const float inv1 = 1.0f / (rs1 + 1e-8f);

    const int bb = bh >> 4;
    const int h  = bh & 15;
    const int sLo = q0 + w * 16 + (lane >> 2);
    #pragma unroll
    for (int f = 0; f < 8; f++) {
        int d0 = f * 8 + (lane & 3) * 2;
        float2 v0, v1;
        v0.x = ctx[f][0] * inv0; v0.y = ctx[f][1] * inv0;
        v1.x = ctx[f][2] * inv1; v1.y = ctx[f][3] * inv1;
        *(float2*)&out[((size_t)(bb * SS + sLo) * DMODEL) + h * DKV + d0]     = v0;
        *(float2*)&out[((size_t)(bb * SS + sLo + 8) * DMODEL) + h * DKV + d0] = v1;
    }
}

// ---------------------------------------------------------------------------
extern "C" void kernel_launch(void* const* d_in, const int* in_sizes, int n_in,
                              void* d_out, int out_size)
{
    const float* Q  = (const float*)d_in[0];
    const float* K  = (const float*)d_in[1];
    const float* V  = (const float*)d_in[2];
    const float* Wq = (const float*)d_in[3];
    const float* bq = (const float*)d_in[4];
    const float* Wk = (const float*)d_in[5];
    const float* bk = (const float*)d_in[6];
    const float* Wv = (const float*)d_in[7];
    const float* bv = (const float*)d_in[8];
    float* out = (float*)d_out;

    cudaFuncSetAttribute(proj_mma_kernel,
                         cudaFuncAttributeMaxDynamicSharedMemorySize, PROJ_SMEM);
    cudaFuncSetAttribute(attn_mma_kernel,
                         cudaFuncAttributeMaxDynamicSharedMemorySize, ATTN_SMEM);

    convert_x_kernel<<<dim3(MTOT * DMODEL / 1024, 3), 256>>>(Q, K, V);
    conv_w_kernel<<<dim3(32, 32, 3), dim3(32, 8)>>>(Wq, Wk, Wv);

    dim3 pg(MTOT / 128, DMODEL / 128, 3);
    proj_mma_kernel<<<pg, 256, PROJ_SMEM>>>(bq, bk, bv);

    dim3 ag(SS / 128, BB * NH);
    attn_mma_kernel<<<ag, 256, ATTN_SMEM>>>(out);
}